// round 1
// baseline (speedup 1.0000x reference)
#include <cuda_runtime.h>
#include <math.h>

#define B 64
#define Cc 100
#define Ff 2048
#define T 32
#define H 300

// ------------------- scratch (static device memory, no allocs) -------------------
__device__ float g_mean[B * Ff];          // mean over C of encoder
__device__ float g_eenc[B * Cc];          // enc @ We_enc
__device__ float g_attn[B * Cc];          // softmax(e_enc)  (time-invariant!)
__device__ float g_ctxT[Ff * B];          // ctx transposed [f][b]
__device__ float g_cT[H * B];             // cell state [hh][b]
__device__ float g_hT[2][H * B];          // hidden state double-buffered [hh][b]
__device__ float g_CWT[1504 * B];         // ctx @ [Wi|Wf|Wo|Wg ctx-rows, Wcp], [j][b]
__device__ float g_baseT[31 * 1200 * B];  // per-step gate pre-act base [t][j][b]
__device__ float g_sbT[31 * H * B];       // sbase [t][k][b]
__device__ float g_pbT[31 * H * B];       // pbase = sbase@Wop + bop, [t][jj][b]
__device__ float g_WW[H * H];             // Whp @ Wop

// ------------------- prologue kernels -------------------

__global__ void k_mean(const float* __restrict__ enc) {
    int idx = blockIdx.x * 256 + threadIdx.x;       // 131072 threads
    int b = idx >> 11, f = idx & 2047;
    const float* p = enc + (size_t)b * Cc * Ff + f;
    float s = 0.f;
#pragma unroll 4
    for (int c = 0; c < Cc; c++) s += p[c * Ff];
    g_mean[idx] = s * (1.0f / Cc);
}

__global__ void k_eenc(const float* __restrict__ enc, const float* __restrict__ We) {
    int idx = blockIdx.x * 256 + threadIdx.x;       // 6400 threads
    if (idx >= B * Cc) return;
    const float4* row = (const float4*)(enc + (size_t)idx * Ff);
    const float4* w = (const float4*)We;
    float s = 0.f;
#pragma unroll 4
    for (int i = 0; i < Ff / 4; i++) {
        float4 a = row[i], c4 = w[i];
        s += a.x * c4.x + a.y * c4.y + a.z * c4.z + a.w * c4.w;
    }
    g_eenc[idx] = s;
}

// softmax over C=100 per batch row. (h-dot and be are constant shifts -> dropped)
__global__ void k_softmax() {
    __shared__ float sv[128];
    int b = blockIdx.x, tid = threadIdx.x;
    float v = (tid < Cc) ? g_eenc[b * Cc + tid] : -1e30f;
    sv[tid] = v;
    __syncthreads();
    for (int s = 64; s > 0; s >>= 1) {
        if (tid < s) sv[tid] = fmaxf(sv[tid], sv[tid + s]);
        __syncthreads();
    }
    float mx = sv[0];
    __syncthreads();
    float e = (tid < Cc) ? expf(v - mx) : 0.f;
    sv[tid] = e;
    __syncthreads();
    for (int s = 64; s > 0; s >>= 1) {
        if (tid < s) sv[tid] += sv[tid + s];
        __syncthreads();
    }
    float inv = 1.0f / sv[0];
    if (tid < Cc) g_attn[b * Cc + tid] = e * inv;
}

__global__ void k_ctx(const float* __restrict__ enc) {
    __shared__ float at[Cc];
    int idx = blockIdx.x * 256 + threadIdx.x;       // 131072 threads; each block one b
    int b = idx >> 11, f = idx & 2047;
    if (threadIdx.x < Cc) at[threadIdx.x] = g_attn[b * Cc + threadIdx.x];
    __syncthreads();
    const float* p = enc + (size_t)b * Cc * Ff + f;
    float s = 0.f;
#pragma unroll 4
    for (int c = 0; c < Cc; c++) s += at[c] * p[c * Ff];
    g_ctxT[f * B + b] = s;
}

__global__ void k_h0c0(const float* __restrict__ Wh0, const float* __restrict__ bh0,
                       const float* __restrict__ Wc0, const float* __restrict__ bc0) {
    __shared__ float xs[Ff];
    int b = blockIdx.x >> 1, which = blockIdx.x & 1;
    const float* W = which ? Wc0 : Wh0;
    const float* bias = which ? bc0 : bh0;
    for (int k = threadIdx.x; k < Ff; k += blockDim.x) xs[k] = g_mean[b * Ff + k];
    __syncthreads();
    int hh = threadIdx.x;
    if (hh < H) {
        float acc = bias[hh];
        const float* w = W + hh;
#pragma unroll 4
        for (int k = 0; k < Ff; k++) acc += xs[k] * w[k * H];
        float v = tanhf(acc);
        if (which) g_cT[hh * B + b] = v;
        else       g_hT[0][hh * B + b] = v;
    }
}

// CWT[j][b] = sum_f ctx[b][f] * Wctx[f][j], j<1200: gate ctx-rows, 1200..1499: Wcp
__global__ void k_cw(const float* __restrict__ Wi, const float* __restrict__ Wf,
                     const float* __restrict__ Wo, const float* __restrict__ Wg,
                     const float* __restrict__ Wcp) {
    int tid = threadIdx.x;              // 320 threads: 5 j-quads x 64 b
    int b = tid & 63, jq = tid >> 6;
    int j0 = blockIdx.x * 20 + jq * 4;  // grid 75 -> j0 < 1500, j0 % 4 == 0
    const float* wbase;
    if (j0 < 1200) {
        int gate = j0 / 300, col = j0 - gate * 300;
        const float* Wx = (gate == 0) ? Wi : (gate == 1) ? Wf : (gate == 2) ? Wo : Wg;
        wbase = Wx + 600 * H + col;     // ctx rows start at comb row 600
    } else {
        wbase = Wcp + (j0 - 1200);
    }
    float a0 = 0, a1 = 0, a2 = 0, a3 = 0;
    const float* xp = g_ctxT + b;
#pragma unroll 4
    for (int f = 0; f < Ff; f++) {
        float x = xp[f * B];
        float4 w = *(const float4*)(wbase + f * H);
        a0 += x * w.x; a1 += x * w.y; a2 += x * w.z; a3 += x * w.w;
    }
    g_CWT[(j0 + 0) * B + b] = a0; g_CWT[(j0 + 1) * B + b] = a1;
    g_CWT[(j0 + 2) * B + b] = a2; g_CWT[(j0 + 3) * B + b] = a3;
}

// baseT[t][j][b] = bias_g[col] + CWT[j][b] + emb[cap[b][t]] @ (gate emb-rows)
__global__ void k_base(const int* __restrict__ caps, const float* __restrict__ emb,
                       const float* __restrict__ Wi, const float* __restrict__ Wf,
                       const float* __restrict__ Wo, const float* __restrict__ Wg,
                       const float* __restrict__ bi, const float* __restrict__ bf,
                       const float* __restrict__ bo, const float* __restrict__ bg) {
    __shared__ float xs[64 * 61];
    __shared__ int cap_s[64];
    int tid = threadIdx.x;              // 320
    int t = blockIdx.y;
    int b = tid & 63, jq = tid >> 6;
    int j0 = blockIdx.x * 20 + jq * 4;  // grid.x=60 -> j0 < 1200
    int gate = j0 / 300, col0 = j0 - gate * 300;
    const float* Wx = (gate == 0) ? Wi : (gate == 1) ? Wf : (gate == 2) ? Wo : Wg;
    const float* bx = (gate == 0) ? bi : (gate == 1) ? bf : (gate == 2) ? bo : bg;
    if (tid < 64) cap_s[tid] = caps[tid * T + t];
    __syncthreads();
    float a0 = bx[col0 + 0] + g_CWT[(j0 + 0) * B + b];
    float a1 = bx[col0 + 1] + g_CWT[(j0 + 1) * B + b];
    float a2 = bx[col0 + 2] + g_CWT[(j0 + 2) * B + b];
    float a3 = bx[col0 + 3] + g_CWT[(j0 + 3) * B + b];
    for (int c0 = 0; c0 < H; c0 += 60) {
        __syncthreads();
        for (int i = tid; i < 64 * 60; i += 320) {
            int bb = i / 60, kk = i - bb * 60;
            xs[bb * 61 + kk] = emb[(size_t)cap_s[bb] * H + c0 + kk];
        }
        __syncthreads();
        const float* wrow = Wx + c0 * H + col0;
#pragma unroll
        for (int kk = 0; kk < 60; kk++) {
            float x = xs[b * 61 + kk];
            float4 w = *(const float4*)(wrow + kk * H);
            a0 += x * w.x; a1 += x * w.y; a2 += x * w.z; a3 += x * w.w;
        }
    }
    int base = t * 1200;
    g_baseT[(base + j0 + 0) * B + b] = a0;
    g_baseT[(base + j0 + 1) * B + b] = a1;
    g_baseT[(base + j0 + 2) * B + b] = a2;
    g_baseT[(base + j0 + 3) * B + b] = a3;
}

// sbT[t][k][b] = emb_t[b][k] + ctx@Wcp[k] + bcp[k] + bhp[k]
__global__ void k_sb(const int* __restrict__ caps, const float* __restrict__ emb,
                     const float* __restrict__ bcp, const float* __restrict__ bhp) {
    int idx = blockIdx.x * 256 + threadIdx.x;
    if (idx >= 31 * H * B) return;
    int b = idx & 63, r = idx >> 6;
    int k = r % H, t = r / H;
    int cap = caps[b * T + t];
    g_sbT[idx] = emb[(size_t)cap * H + k] + g_CWT[(1200 + k) * B + b] + bcp[k] + bhp[k];
}

// pbT[t][jj][b] = bop[jj] + sum_k sbT[t][k][b] * Wop[k][jj]
__global__ void k_pbase(const float* __restrict__ Wop, const float* __restrict__ bop) {
    int tid = threadIdx.x;              // 320
    int t = blockIdx.y;
    int b = tid & 63, jq = tid >> 6;
    int j0 = blockIdx.x * 20 + jq * 4;  // grid.x=15 -> j0 < 300
    float a0 = bop[j0], a1 = bop[j0 + 1], a2 = bop[j0 + 2], a3 = bop[j0 + 3];
    const float* xp = g_sbT + t * H * B + b;
    const float* wrow = Wop + j0;
#pragma unroll 4
    for (int k = 0; k < H; k++) {
        float x = xp[k * B];
        float4 w = *(const float4*)(wrow + k * H);
        a0 += x * w.x; a1 += x * w.y; a2 += x * w.z; a3 += x * w.w;
    }
    int base = t * H;
    g_pbT[(base + j0 + 0) * B + b] = a0;
    g_pbT[(base + j0 + 1) * B + b] = a1;
    g_pbT[(base + j0 + 2) * B + b] = a2;
    g_pbT[(base + j0 + 3) * B + b] = a3;
}

// WW = Whp @ Wop  (300x300)
__global__ void k_ww(const float* __restrict__ Whp, const float* __restrict__ Wop) {
    int idx = blockIdx.x * 256 + threadIdx.x;
    if (idx >= H * H) return;
    int k = idx / H, jj = idx - k * H;
    float s = 0.f;
    const float* a = Whp + k * H;
    const float* w = Wop + jj;
#pragma unroll 4
    for (int m = 0; m < H; m++) s += a[m] * w[m * H];
    g_WW[idx] = s;
}

__global__ void k_out0(const float* __restrict__ emb, float* __restrict__ out) {
    int idx = blockIdx.x * 256 + threadIdx.x;
    if (idx >= B * H) return;
    int b = idx / H, jj = idx - b * H;
    out[(size_t)b * T * H + jj] = emb[1 * H + jj];   // BOS = 1
}

// ------------------- sequential step kernel (one launch per t, 32 total) -------------------
// Fuses: pred[t] (uses entry h = h_new[t-1]) and gates/LSTM update for step t.
__global__ void k_step(int t,
                       const float* __restrict__ Wi, const float* __restrict__ Wf,
                       const float* __restrict__ Wo, const float* __restrict__ Wg,
                       float* __restrict__ out) {
    int tid = threadIdx.x;               // 128 = 2 hh x 64 b
    int b = tid & 63, hq = tid >> 6;
    int hh = blockIdx.x * 2 + hq;        // grid 150 -> hh < 300
    const float* xin = g_hT[t & 1];
    float ai = 0.f, afv = 0.f, aov = 0.f, agv = 0.f, ap = 0.f;
    if (t < 31) {
        int base = t * 1200;
        ai  = g_baseT[(base +       hh) * B + b];
        afv = g_baseT[(base + 300 + hh) * B + b];
        aov = g_baseT[(base + 600 + hh) * B + b];
        agv = g_baseT[(base + 900 + hh) * B + b];
    }
    if (t > 0) ap = g_pbT[((t - 1) * H + hh) * B + b];
    const float* wi = Wi + 300 * H + hh;   // h rows of comb start at 300
    const float* wf = Wf + 300 * H + hh;
    const float* wo = Wo + 300 * H + hh;
    const float* wg = Wg + 300 * H + hh;
    const float* wp = g_WW + hh;
    const float* xp = xin + b;
#pragma unroll 4
    for (int k = 0; k < H; k++) {
        float x = xp[k * B];
        ai  += x * wi[k * H];
        afv += x * wf[k * H];
        aov += x * wo[k * H];
        agv += x * wg[k * H];
        ap  += x * wp[k * H];
    }
    if (t > 0) out[((size_t)b * T + t) * H + hh] = ap;
    if (t < 31) {
        float iv = 1.f / (1.f + expf(-ai));
        float fv = 1.f / (1.f + expf(-afv));
        float ov = 1.f / (1.f + expf(-aov));
        float gv = tanhf(agv);
        float cc = g_cT[hh * B + b];
        float cn = fv * cc + iv * gv;
        g_cT[hh * B + b] = cn;
        g_hT[(t + 1) & 1][hh * B + b] = ov * tanhf(cn);
    }
}

// ------------------- launch -------------------
extern "C" void kernel_launch(void* const* d_in, const int* in_sizes, int n_in,
                              void* d_out, int out_size) {
    const float* enc    = (const float*)d_in[0];
    const int*   caps   = (const int*)d_in[1];
    const float* emb    = (const float*)d_in[2];
    const float* Wh0    = (const float*)d_in[3];
    const float* bh0    = (const float*)d_in[4];
    const float* Wc0    = (const float*)d_in[5];
    const float* bc0    = (const float*)d_in[6];
    const float* We_enc = (const float*)d_in[7];
    // d_in[8] We_hid, d_in[9] be: unused — constant shifts inside softmax cancel.
    const float* Wi  = (const float*)d_in[10];
    const float* bi  = (const float*)d_in[11];
    const float* Wf  = (const float*)d_in[12];
    const float* bf  = (const float*)d_in[13];
    const float* Wo  = (const float*)d_in[14];
    const float* bo  = (const float*)d_in[15];
    const float* Wg  = (const float*)d_in[16];
    const float* bg  = (const float*)d_in[17];
    const float* Wcp = (const float*)d_in[18];
    const float* bcp = (const float*)d_in[19];
    const float* Whp = (const float*)d_in[20];
    const float* bhp = (const float*)d_in[21];
    const float* Wop = (const float*)d_in[22];
    const float* bop = (const float*)d_in[23];
    float* out = (float*)d_out;

    k_mean<<<512, 256>>>(enc);
    k_eenc<<<25, 256>>>(enc, We_enc);
    k_softmax<<<64, 128>>>();
    k_ctx<<<512, 256>>>(enc);
    k_h0c0<<<128, 320>>>(Wh0, bh0, Wc0, bc0);
    k_cw<<<75, 320>>>(Wi, Wf, Wo, Wg, Wcp);
    {
        dim3 gb(60, 31);
        k_base<<<gb, 320>>>(caps, emb, Wi, Wf, Wo, Wg, bi, bf, bo, bg);
    }
    k_sb<<<(31 * H * B + 255) / 256, 256>>>(caps, emb, bcp, bhp);
    {
        dim3 gp(15, 31);
        k_pbase<<<gp, 320>>>(Wop, bop);
    }
    k_ww<<<(H * H + 255) / 256, 256>>>(Whp, Wop);
    k_out0<<<(B * H + 255) / 256, 256>>>(emb, out);

    for (int t = 0; t < 32; t++)
        k_step<<<150, 128>>>(t, Wi, Wf, Wo, Wg, out);
}

// round 2
// speedup vs baseline: 2.8840x; 2.8840x over previous
#include <cuda_runtime.h>
#include <math.h>

#define B 64
#define Cc 100
#define Ff 2048
#define T 32
#define H 300
#define NBLK 150   // persistent step-kernel grid

// ------------------- scratch (static device memory, no allocs) -------------------
__device__ float g_mean[B * Ff];          // mean over C of encoder
__device__ float g_eenc[B * Cc];          // enc @ We_enc
__device__ float g_attn[B * Cc];          // softmax(e_enc)  (time-invariant!)
__device__ float g_ctxT[Ff * B];          // ctx transposed [f][b]
__device__ float g_cT[H * B];             // cell state [hh][b]
__device__ float g_hT[2][H * B];          // hidden state double-buffered [hh][b]
__device__ float g_CWT[1504 * B];         // ctx @ [Wi|Wf|Wo|Wg ctx-rows, Wcp], [j][b]
__device__ float g_baseT[31 * 1200 * B];  // per-step gate pre-act base [t][j][b]
__device__ float g_sbT[31 * H * B];       // sbase [t][k][b]
__device__ float g_pbT[31 * H * B];       // pbase = sbase@Wop + bop, [t][jj][b]
__device__ float g_WW[H * H];             // Whp @ Wop
__device__ unsigned g_cnt;                // grid-sync counter (reset each launch in k_ww)

// ------------------- prologue kernels -------------------

__global__ void k_mean(const float* __restrict__ enc) {
    int idx = blockIdx.x * 256 + threadIdx.x;       // 131072 threads
    int b = idx >> 11, f = idx & 2047;
    const float* p = enc + (size_t)b * Cc * Ff + f;
    float s = 0.f;
#pragma unroll 4
    for (int c = 0; c < Cc; c++) s += p[c * Ff];
    g_mean[idx] = s * (1.0f / Cc);
}

__global__ void k_eenc(const float* __restrict__ enc, const float* __restrict__ We) {
    int idx = blockIdx.x * 256 + threadIdx.x;       // 6400 threads
    if (idx >= B * Cc) return;
    const float4* row = (const float4*)(enc + (size_t)idx * Ff);
    const float4* w = (const float4*)We;
    float s = 0.f;
#pragma unroll 4
    for (int i = 0; i < Ff / 4; i++) {
        float4 a = row[i], c4 = w[i];
        s += a.x * c4.x + a.y * c4.y + a.z * c4.z + a.w * c4.w;
    }
    g_eenc[idx] = s;
}

// softmax over C=100 per batch row. (h-dot and be are constant shifts -> dropped)
__global__ void k_softmax() {
    __shared__ float sv[128];
    int b = blockIdx.x, tid = threadIdx.x;
    float v = (tid < Cc) ? g_eenc[b * Cc + tid] : -1e30f;
    sv[tid] = v;
    __syncthreads();
    for (int s = 64; s > 0; s >>= 1) {
        if (tid < s) sv[tid] = fmaxf(sv[tid], sv[tid + s]);
        __syncthreads();
    }
    float mx = sv[0];
    __syncthreads();
    float e = (tid < Cc) ? expf(v - mx) : 0.f;
    sv[tid] = e;
    __syncthreads();
    for (int s = 64; s > 0; s >>= 1) {
        if (tid < s) sv[tid] += sv[tid + s];
        __syncthreads();
    }
    float inv = 1.0f / sv[0];
    if (tid < Cc) g_attn[b * Cc + tid] = e * inv;
}

__global__ void k_ctx(const float* __restrict__ enc) {
    __shared__ float at[Cc];
    int idx = blockIdx.x * 256 + threadIdx.x;       // 131072 threads
    int b = idx >> 11, f = idx & 2047;
    if (threadIdx.x < Cc) at[threadIdx.x] = g_attn[b * Cc + threadIdx.x];
    __syncthreads();
    const float* p = enc + (size_t)b * Cc * Ff + f;
    float s = 0.f;
#pragma unroll 4
    for (int c = 0; c < Cc; c++) s += at[c] * p[c * Ff];
    g_ctxT[f * B + b] = s;
}

__global__ void k_h0c0(const float* __restrict__ Wh0, const float* __restrict__ bh0,
                       const float* __restrict__ Wc0, const float* __restrict__ bc0) {
    __shared__ float xs[Ff];
    int b = blockIdx.x >> 1, which = blockIdx.x & 1;
    const float* W = which ? Wc0 : Wh0;
    const float* bias = which ? bc0 : bh0;
    for (int k = threadIdx.x; k < Ff; k += blockDim.x) xs[k] = g_mean[b * Ff + k];
    __syncthreads();
    int hh = threadIdx.x;
    if (hh < H) {
        float acc = bias[hh];
        const float* w = W + hh;
#pragma unroll 4
        for (int k = 0; k < Ff; k++) acc += xs[k] * w[k * H];
        float v = tanhf(acc);
        if (which) g_cT[hh * B + b] = v;
        else       g_hT[0][hh * B + b] = v;
    }
}

// CWT[j][b] = sum_f ctx[b][f] * Wctx[f][j], j<1200: gate ctx-rows, 1200..1499: Wcp
__global__ void k_cw(const float* __restrict__ Wi, const float* __restrict__ Wf,
                     const float* __restrict__ Wo, const float* __restrict__ Wg,
                     const float* __restrict__ Wcp) {
    int tid = threadIdx.x;              // 320 threads: 5 j-quads x 64 b
    int b = tid & 63, jq = tid >> 6;
    int j0 = blockIdx.x * 20 + jq * 4;  // grid 75 -> j0 < 1500, j0 % 4 == 0
    const float* wbase;
    if (j0 < 1200) {
        int gate = j0 / 300, col = j0 - gate * 300;
        const float* Wx = (gate == 0) ? Wi : (gate == 1) ? Wf : (gate == 2) ? Wo : Wg;
        wbase = Wx + 600 * H + col;     // ctx rows start at comb row 600
    } else {
        wbase = Wcp + (j0 - 1200);
    }
    float a0 = 0, a1 = 0, a2 = 0, a3 = 0;
    const float* xp = g_ctxT + b;
#pragma unroll 4
    for (int f = 0; f < Ff; f++) {
        float x = xp[f * B];
        float4 w = *(const float4*)(wbase + f * H);
        a0 += x * w.x; a1 += x * w.y; a2 += x * w.z; a3 += x * w.w;
    }
    g_CWT[(j0 + 0) * B + b] = a0; g_CWT[(j0 + 1) * B + b] = a1;
    g_CWT[(j0 + 2) * B + b] = a2; g_CWT[(j0 + 3) * B + b] = a3;
}

// baseT[t][j][b] = bias_g[col] + CWT[j][b] + emb[cap[b][t]] @ (gate emb-rows)
__global__ void k_base(const int* __restrict__ caps, const float* __restrict__ emb,
                       const float* __restrict__ Wi, const float* __restrict__ Wf,
                       const float* __restrict__ Wo, const float* __restrict__ Wg,
                       const float* __restrict__ bi, const float* __restrict__ bf,
                       const float* __restrict__ bo, const float* __restrict__ bg) {
    __shared__ float xs[64 * 61];
    __shared__ int cap_s[64];
    int tid = threadIdx.x;              // 320
    int t = blockIdx.y;
    int b = tid & 63, jq = tid >> 6;
    int j0 = blockIdx.x * 20 + jq * 4;  // grid.x=60 -> j0 < 1200
    int gate = j0 / 300, col0 = j0 - gate * 300;
    const float* Wx = (gate == 0) ? Wi : (gate == 1) ? Wf : (gate == 2) ? Wo : Wg;
    const float* bx = (gate == 0) ? bi : (gate == 1) ? bf : (gate == 2) ? bo : bg;
    if (tid < 64) cap_s[tid] = caps[tid * T + t];
    __syncthreads();
    float a0 = bx[col0 + 0] + g_CWT[(j0 + 0) * B + b];
    float a1 = bx[col0 + 1] + g_CWT[(j0 + 1) * B + b];
    float a2 = bx[col0 + 2] + g_CWT[(j0 + 2) * B + b];
    float a3 = bx[col0 + 3] + g_CWT[(j0 + 3) * B + b];
    for (int c0 = 0; c0 < H; c0 += 60) {
        __syncthreads();
        for (int i = tid; i < 64 * 60; i += 320) {
            int bb = i / 60, kk = i - bb * 60;
            xs[bb * 61 + kk] = emb[(size_t)cap_s[bb] * H + c0 + kk];
        }
        __syncthreads();
        const float* wrow = Wx + c0 * H + col0;
#pragma unroll 10
        for (int kk = 0; kk < 60; kk++) {
            float x = xs[b * 61 + kk];
            float4 w = *(const float4*)(wrow + kk * H);
            a0 += x * w.x; a1 += x * w.y; a2 += x * w.z; a3 += x * w.w;
        }
    }
    int base = t * 1200;
    g_baseT[(base + j0 + 0) * B + b] = a0;
    g_baseT[(base + j0 + 1) * B + b] = a1;
    g_baseT[(base + j0 + 2) * B + b] = a2;
    g_baseT[(base + j0 + 3) * B + b] = a3;
}

// sbT[t][k][b] = emb_t[b][k] + ctx@Wcp[k] + bcp[k] + bhp[k]
__global__ void k_sb(const int* __restrict__ caps, const float* __restrict__ emb,
                     const float* __restrict__ bcp, const float* __restrict__ bhp) {
    int idx = blockIdx.x * 256 + threadIdx.x;
    if (idx >= 31 * H * B) return;
    int b = idx & 63, r = idx >> 6;
    int k = r % H, t = r / H;
    int cap = caps[b * T + t];
    g_sbT[idx] = emb[(size_t)cap * H + k] + g_CWT[(1200 + k) * B + b] + bcp[k] + bhp[k];
}

// pbT[t][jj][b] = bop[jj] + sum_k sbT[t][k][b] * Wop[k][jj]
__global__ void k_pbase(const float* __restrict__ Wop, const float* __restrict__ bop) {
    int tid = threadIdx.x;              // 320
    int t = blockIdx.y;
    int b = tid & 63, jq = tid >> 6;
    int j0 = blockIdx.x * 20 + jq * 4;  // grid.x=15 -> j0 < 300
    float a0 = bop[j0], a1 = bop[j0 + 1], a2 = bop[j0 + 2], a3 = bop[j0 + 3];
    const float* xp = g_sbT + t * H * B + b;
    const float* wrow = Wop + j0;
#pragma unroll 4
    for (int k = 0; k < H; k++) {
        float x = xp[k * B];
        float4 w = *(const float4*)(wrow + k * H);
        a0 += x * w.x; a1 += x * w.y; a2 += x * w.z; a3 += x * w.w;
    }
    int base = t * H;
    g_pbT[(base + j0 + 0) * B + b] = a0;
    g_pbT[(base + j0 + 1) * B + b] = a1;
    g_pbT[(base + j0 + 2) * B + b] = a2;
    g_pbT[(base + j0 + 3) * B + b] = a3;
}

// WW = Whp @ Wop  (300x300); also resets the grid-sync counter for this launch
__global__ void k_ww(const float* __restrict__ Whp, const float* __restrict__ Wop) {
    int idx = blockIdx.x * 256 + threadIdx.x;
    if (idx == 0) g_cnt = 0;
    if (idx >= H * H) return;
    int k = idx / H, jj = idx - k * H;
    float s = 0.f;
    const float* a = Whp + k * H;
    const float* w = Wop + jj;
#pragma unroll 4
    for (int m = 0; m < H; m++) s += a[m] * w[m * H];
    g_WW[idx] = s;
}

__global__ void k_out0(const float* __restrict__ emb, float* __restrict__ out) {
    int idx = blockIdx.x * 256 + threadIdx.x;
    if (idx >= B * H) return;
    int b = idx / H, jj = idx - b * H;
    out[(size_t)b * T * H + jj] = emb[1 * H + jj];   // BOS = 1
}

// ------------------- persistent recurrence kernel (ONE launch, 32 steps) -------------------
// 150 blocks x 320 threads; block owns 2 hh columns for all 5 matrices (i,f,o,g, WW).
// Weights staged in SMEM once; h exchanged through global double buffer with a
// monotonic-counter grid barrier per step; x loads use __ldcg (L1 would go stale).
__global__ void __launch_bounds__(320, 2) k_steps(
        const float* __restrict__ Wi, const float* __restrict__ Wf,
        const float* __restrict__ Wo, const float* __restrict__ Wg,
        float* __restrict__ out) {
    __shared__ float sw[H * 10];      // [k][m*2+j], 12 KB
    __shared__ float ex[4 * 128];     // gate exchange [m][j*64+b]
    __shared__ float cs[128];         // cell state [j*64+b]

    int tid = threadIdx.x;
    int b = tid & 63, m = tid >> 6;        // m in [0,5)
    int hh0 = blockIdx.x * 2;              // 2 hh per block

    // ---- stage this block's weight slice into smem (once) ----
    for (int idx = tid; idx < H * 10; idx += 320) {
        int k = idx / 10, r = idx - k * 10;
        int mm = r >> 1, j = r & 1;
        float v;
        if (mm < 4) {
            const float* Wx = (mm == 0) ? Wi : (mm == 1) ? Wf : (mm == 2) ? Wo : Wg;
            v = Wx[(300 + k) * H + hh0 + j];   // h rows of comb start at 300
        } else {
            v = g_WW[k * H + hh0 + j];
        }
        sw[idx] = v;
    }
    if (tid < 128) {
        int j = tid >> 6, bb = tid & 63;
        cs[tid] = g_cT[(hh0 + j) * B + bb];
    }
    __syncthreads();

    for (int t = 0; t < T; t++) {
        // ---- init accumulators from precomputed bases ----
        float a0, a1;
        if (m < 4) {
            if (t < 31) {
                int base = (t * 1200 + m * 300 + hh0) * B + b;
                a0 = g_baseT[base];
                a1 = g_baseT[base + B];
            } else { a0 = 0.f; a1 = 0.f; }
        } else {
            if (t > 0) {
                int base = ((t - 1) * H + hh0) * B + b;
                a0 = g_pbT[base];
                a1 = g_pbT[base + B];
            } else { a0 = 0.f; a1 = 0.f; }
        }

        // ---- dot over K=300: x from global (L2), weights from smem ----
        const float* xb = g_hT[t & 1] + b;
        const float* wb = sw + m * 2;
#pragma unroll 10
        for (int k = 0; k < H; k++) {
            float x = __ldcg(xb + k * B);
            float2 w = *(const float2*)(wb + k * 10);
            a0 = fmaf(x, w.x, a0);
            a1 = fmaf(x, w.y, a1);
        }

        // ---- pred output (m==4) ----
        if (m == 4 && t > 0) {
            out[((size_t)b * T + t) * H + hh0 + 0] = a0;
            out[((size_t)b * T + t) * H + hh0 + 1] = a1;
        }

        if (t < 31) {
            // ---- exchange gate pre-acts, pointwise LSTM update ----
            if (m < 4) {
                ex[m * 128 + b]      = a0;
                ex[m * 128 + 64 + b] = a1;
            }
            __syncthreads();
            if (tid < 128) {
                int j = tid >> 6, bb = tid & 63;
                float ai = ex[tid];
                float af = ex[128 + tid];
                float ao = ex[256 + tid];
                float ag = ex[384 + tid];
                float iv = 1.f / (1.f + expf(-ai));
                float fv = 1.f / (1.f + expf(-af));
                float ov = 1.f / (1.f + expf(-ao));
                float gv = tanhf(ag);
                float cn = fv * cs[tid] + iv * gv;
                cs[tid] = cn;
                g_hT[(t + 1) & 1][(hh0 + j) * B + bb] = ov * tanhf(cn);
            }
            // ---- grid barrier: all h writes visible before next step's reads ----
            __threadfence();
            __syncthreads();
            if (tid == 0) {
                atomicAdd(&g_cnt, 1u);
                unsigned target = (unsigned)NBLK * (unsigned)(t + 1);
                while (*((volatile unsigned*)&g_cnt) < target) { }
            }
            __syncthreads();
        }
    }
}

// ------------------- launch -------------------
extern "C" void kernel_launch(void* const* d_in, const int* in_sizes, int n_in,
                              void* d_out, int out_size) {
    const float* enc    = (const float*)d_in[0];
    const int*   caps   = (const int*)d_in[1];
    const float* emb    = (const float*)d_in[2];
    const float* Wh0    = (const float*)d_in[3];
    const float* bh0    = (const float*)d_in[4];
    const float* Wc0    = (const float*)d_in[5];
    const float* bc0    = (const float*)d_in[6];
    const float* We_enc = (const float*)d_in[7];
    // d_in[8] We_hid, d_in[9] be: unused — constant shifts inside softmax cancel.
    const float* Wi  = (const float*)d_in[10];
    const float* bi  = (const float*)d_in[11];
    const float* Wf  = (const float*)d_in[12];
    const float* bf  = (const float*)d_in[13];
    const float* Wo  = (const float*)d_in[14];
    const float* bo  = (const float*)d_in[15];
    const float* Wg  = (const float*)d_in[16];
    const float* bg  = (const float*)d_in[17];
    const float* Wcp = (const float*)d_in[18];
    const float* bcp = (const float*)d_in[19];
    const float* Whp = (const float*)d_in[20];
    const float* bhp = (const float*)d_in[21];
    const float* Wop = (const float*)d_in[22];
    const float* bop = (const float*)d_in[23];
    float* out = (float*)d_out;

    k_mean<<<512, 256>>>(enc);
    k_eenc<<<25, 256>>>(enc, We_enc);
    k_softmax<<<64, 128>>>();
    k_ctx<<<512, 256>>>(enc);
    k_h0c0<<<128, 320>>>(Wh0, bh0, Wc0, bc0);
    k_cw<<<75, 320>>>(Wi, Wf, Wo, Wg, Wcp);
    {
        dim3 gb(60, 31);
        k_base<<<gb, 320>>>(caps, emb, Wi, Wf, Wo, Wg, bi, bf, bo, bg);
    }
    k_sb<<<(31 * H * B + 255) / 256, 256>>>(caps, emb, bcp, bhp);
    {
        dim3 gp(15, 31);
        k_pbase<<<gp, 320>>>(Wop, bop);
    }
    k_ww<<<(H * H + 255) / 256, 256>>>(Whp, Wop);
    k_out0<<<(B * H + 255) / 256, 256>>>(emb, out);

    k_steps<<<NBLK, 320>>>(Wi, Wf, Wo, Wg, out);
}

// round 3
// speedup vs baseline: 3.0199x; 1.0471x over previous
#include <cuda_runtime.h>
#include <math.h>

#define B 64
#define Cc 100
#define Ff 2048
#define T 32
#define H 300
#define NBLK 150   // persistent step-kernel grid

// ------------------- scratch (static device memory, no allocs) -------------------
__device__ float g_mean[B * Ff];          // mean over C of encoder
__device__ float g_eenc[B * Cc];          // enc @ We_enc
__device__ float g_attn[B * Cc];          // softmax(e_enc)  (time-invariant!)
__device__ float g_ctxT[Ff * B];          // ctx transposed [f][b]
__device__ float g_cT[H * B];             // cell state init [hh][b]
__device__ float g_hS[T][H * B];          // hidden state, FRESH buffer per step (L1-safe)
__device__ float g_CWT[1504 * B];         // ctx @ [Wi|Wf|Wo|Wg ctx-rows, Wcp], [j][b]
__device__ float g_baseT[31 * 1200 * B];  // per-step gate pre-act base [t][j][b]
__device__ float g_sbT[31 * H * B];       // sbase [t][k][b]
__device__ float g_pbT[31 * H * B];       // pbase = sbase@Wop + bop, [t][jj][b]
__device__ float g_WW[H * H];             // Whp @ Wop
__device__ unsigned g_cnt;                // grid-sync counter (reset each launch in k_ww)

// ------------------- prologue kernels -------------------

// one warp per (b,c) row: coalesced 512B/warp-load + shuffle reduce
__global__ void k_eenc(const float* __restrict__ enc, const float* __restrict__ We) {
    int w = blockIdx.x * 4 + (threadIdx.x >> 5);    // 1600 blocks x 128
    int lane = threadIdx.x & 31;
    if (w >= B * Cc) return;
    const float4* row = (const float4*)(enc + (size_t)w * Ff);
    const float4* wv = (const float4*)We;
    float s = 0.f;
#pragma unroll
    for (int i = 0; i < Ff / 4; i += 32) {
        float4 a = row[i + lane], c4 = wv[i + lane];
        s += a.x * c4.x + a.y * c4.y + a.z * c4.z + a.w * c4.w;
    }
#pragma unroll
    for (int o = 16; o > 0; o >>= 1) s += __shfl_down_sync(0xffffffffu, s, o);
    if (lane == 0) g_eenc[w] = s;
}

// softmax over C=100 per batch row. (h-dot and be are constant shifts -> dropped)
__global__ void k_softmax() {
    __shared__ float sv[128];
    int b = blockIdx.x, tid = threadIdx.x;
    float v = (tid < Cc) ? g_eenc[b * Cc + tid] : -1e30f;
    sv[tid] = v;
    __syncthreads();
    for (int s = 64; s > 0; s >>= 1) {
        if (tid < s) sv[tid] = fmaxf(sv[tid], sv[tid + s]);
        __syncthreads();
    }
    float mx = sv[0];
    __syncthreads();
    float e = (tid < Cc) ? expf(v - mx) : 0.f;
    sv[tid] = e;
    __syncthreads();
    for (int s = 64; s > 0; s >>= 1) {
        if (tid < s) sv[tid] += sv[tid + s];
        __syncthreads();
    }
    float inv = 1.0f / sv[0];
    if (tid < Cc) g_attn[b * Cc + tid] = e * inv;
}

// fused: ctx (attn-weighted sum over c) AND mean (uniform sum over c) in ONE 52MB scan
__global__ void k_meanctx(const float* __restrict__ enc) {
    __shared__ float at[Cc];
    int idx = blockIdx.x * 256 + threadIdx.x;       // 131072 threads, 8 blocks per b
    int b = idx >> 11, f = idx & 2047;
    if (threadIdx.x < Cc) at[threadIdx.x] = g_attn[b * Cc + threadIdx.x];
    __syncthreads();
    const float* p = enc + (size_t)b * Cc * Ff + f;
    float sc = 0.f, sm = 0.f;
#pragma unroll 4
    for (int c = 0; c < Cc; c++) {
        float v = p[c * Ff];
        sc = fmaf(at[c], v, sc);
        sm += v;
    }
    g_ctxT[f * B + b] = sc;
    g_mean[idx] = sm * (1.0f / Cc);
}

__global__ void k_h0c0(const float* __restrict__ Wh0, const float* __restrict__ bh0,
                       const float* __restrict__ Wc0, const float* __restrict__ bc0) {
    __shared__ float xs[Ff];
    int b = blockIdx.x >> 1, which = blockIdx.x & 1;
    const float* W = which ? Wc0 : Wh0;
    const float* bias = which ? bc0 : bh0;
    for (int k = threadIdx.x; k < Ff; k += blockDim.x) xs[k] = g_mean[b * Ff + k];
    __syncthreads();
    int hh = threadIdx.x;
    if (hh < H) {
        float acc = bias[hh];
        const float* w = W + hh;
#pragma unroll 4
        for (int k = 0; k < Ff; k++) acc += xs[k] * w[k * H];
        float v = tanhf(acc);
        if (which) g_cT[hh * B + b] = v;
        else       g_hS[0][hh * B + b] = v;
    }
}

// CWT[j][b] = sum_f ctx[b][f] * Wctx[f][j], j<1200: gate ctx-rows, 1200..1499: Wcp
__global__ void k_cw(const float* __restrict__ Wi, const float* __restrict__ Wf,
                     const float* __restrict__ Wo, const float* __restrict__ Wg,
                     const float* __restrict__ Wcp) {
    int tid = threadIdx.x;              // 320 threads: 5 j-quads x 64 b
    int b = tid & 63, jq = tid >> 6;
    int j0 = blockIdx.x * 20 + jq * 4;  // grid 75 -> j0 < 1500, j0 % 4 == 0
    const float* wbase;
    if (j0 < 1200) {
        int gate = j0 / 300, col = j0 - gate * 300;
        const float* Wx = (gate == 0) ? Wi : (gate == 1) ? Wf : (gate == 2) ? Wo : Wg;
        wbase = Wx + 600 * H + col;     // ctx rows start at comb row 600
    } else {
        wbase = Wcp + (j0 - 1200);
    }
    float a0 = 0, a1 = 0, a2 = 0, a3 = 0;
    const float* xp = g_ctxT + b;
#pragma unroll 4
    for (int f = 0; f < Ff; f++) {
        float x = xp[f * B];
        float4 w = *(const float4*)(wbase + f * H);
        a0 += x * w.x; a1 += x * w.y; a2 += x * w.z; a3 += x * w.w;
    }
    g_CWT[(j0 + 0) * B + b] = a0; g_CWT[(j0 + 1) * B + b] = a1;
    g_CWT[(j0 + 2) * B + b] = a2; g_CWT[(j0 + 3) * B + b] = a3;
}

// baseT[t][j][b] = bias_g[col] + CWT[j][b] + emb[cap[b][t]] @ (gate emb-rows)
__global__ void k_base(const int* __restrict__ caps, const float* __restrict__ emb,
                       const float* __restrict__ Wi, const float* __restrict__ Wf,
                       const float* __restrict__ Wo, const float* __restrict__ Wg,
                       const float* __restrict__ bi, const float* __restrict__ bf,
                       const float* __restrict__ bo, const float* __restrict__ bg) {
    __shared__ float xs[64 * 61];
    __shared__ int cap_s[64];
    int tid = threadIdx.x;              // 320
    int t = blockIdx.y;
    int b = tid & 63, jq = tid >> 6;
    int j0 = blockIdx.x * 20 + jq * 4;  // grid.x=60 -> j0 < 1200
    int gate = j0 / 300, col0 = j0 - gate * 300;
    const float* Wx = (gate == 0) ? Wi : (gate == 1) ? Wf : (gate == 2) ? Wo : Wg;
    const float* bx = (gate == 0) ? bi : (gate == 1) ? bf : (gate == 2) ? bo : bg;
    if (tid < 64) cap_s[tid] = caps[tid * T + t];
    __syncthreads();
    float a0 = bx[col0 + 0] + g_CWT[(j0 + 0) * B + b];
    float a1 = bx[col0 + 1] + g_CWT[(j0 + 1) * B + b];
    float a2 = bx[col0 + 2] + g_CWT[(j0 + 2) * B + b];
    float a3 = bx[col0 + 3] + g_CWT[(j0 + 3) * B + b];
    for (int c0 = 0; c0 < H; c0 += 60) {
        __syncthreads();
        for (int i = tid; i < 64 * 60; i += 320) {
            int bb = i / 60, kk = i - bb * 60;
            xs[bb * 61 + kk] = emb[(size_t)cap_s[bb] * H + c0 + kk];
        }
        __syncthreads();
        const float* wrow = Wx + c0 * H + col0;
#pragma unroll 10
        for (int kk = 0; kk < 60; kk++) {
            float x = xs[b * 61 + kk];
            float4 w = *(const float4*)(wrow + kk * H);
            a0 += x * w.x; a1 += x * w.y; a2 += x * w.z; a3 += x * w.w;
        }
    }
    int base = t * 1200;
    g_baseT[(base + j0 + 0) * B + b] = a0;
    g_baseT[(base + j0 + 1) * B + b] = a1;
    g_baseT[(base + j0 + 2) * B + b] = a2;
    g_baseT[(base + j0 + 3) * B + b] = a3;
}

// sbT[t][k][b] = emb_t[b][k] + ctx@Wcp[k] + bcp[k] + bhp[k]
__global__ void k_sb(const int* __restrict__ caps, const float* __restrict__ emb,
                     const float* __restrict__ bcp, const float* __restrict__ bhp) {
    int idx = blockIdx.x * 256 + threadIdx.x;
    if (idx >= 31 * H * B) return;
    int b = idx & 63, r = idx >> 6;
    int k = r % H, t = r / H;
    int cap = caps[b * T + t];
    g_sbT[idx] = emb[(size_t)cap * H + k] + g_CWT[(1200 + k) * B + b] + bcp[k] + bhp[k];
}

// pbT[t][jj][b] = bop[jj] + sum_k sbT[t][k][b] * Wop[k][jj]
__global__ void k_pbase(const float* __restrict__ Wop, const float* __restrict__ bop) {
    int tid = threadIdx.x;              // 320
    int t = blockIdx.y;
    int b = tid & 63, jq = tid >> 6;
    int j0 = blockIdx.x * 20 + jq * 4;  // grid.x=15 -> j0 < 300
    float a0 = bop[j0], a1 = bop[j0 + 1], a2 = bop[j0 + 2], a3 = bop[j0 + 3];
    const float* xp = g_sbT + t * H * B + b;
    const float* wrow = Wop + j0;
#pragma unroll 4
    for (int k = 0; k < H; k++) {
        float x = xp[k * B];
        float4 w = *(const float4*)(wrow + k * H);
        a0 += x * w.x; a1 += x * w.y; a2 += x * w.z; a3 += x * w.w;
    }
    int base = t * H;
    g_pbT[(base + j0 + 0) * B + b] = a0;
    g_pbT[(base + j0 + 1) * B + b] = a1;
    g_pbT[(base + j0 + 2) * B + b] = a2;
    g_pbT[(base + j0 + 3) * B + b] = a3;
}

// WW = Whp @ Wop  (300x300); also resets the grid-sync counter for this launch
__global__ void k_ww(const float* __restrict__ Whp, const float* __restrict__ Wop) {
    int idx = blockIdx.x * 256 + threadIdx.x;
    if (idx == 0) g_cnt = 0;
    if (idx >= H * H) return;
    int k = idx / H, jj = idx - k * H;
    float s = 0.f;
    const float* a = Whp + k * H;
    const float* w = Wop + jj;
#pragma unroll 4
    for (int m = 0; m < H; m++) s += a[m] * w[m * H];
    g_WW[idx] = s;
}

__global__ void k_out0(const float* __restrict__ emb, float* __restrict__ out) {
    int idx = blockIdx.x * 256 + threadIdx.x;
    if (idx >= B * H) return;
    int b = idx / H, jj = idx - b * H;
    out[(size_t)b * T * H + jj] = emb[1 * H + jj];   // BOS = 1
}

// ------------------- persistent recurrence kernel (ONE launch, 32 steps) -------------------
// 150 blocks x 320 threads; block owns 2 hh columns for all 5 matrices (i,f,o,g, WW).
// Weights staged in SMEM once. Each step reads h from a FRESH global buffer g_hS[t]
// (never-before-read addresses -> L1 cannot hold stale data; L1D flushed per launch,
// so graph replays are safe too). First warp misses to L2, sibling warps hit L1.
__global__ void __launch_bounds__(320, 2) k_steps(
        const float* __restrict__ Wi, const float* __restrict__ Wf,
        const float* __restrict__ Wo, const float* __restrict__ Wg,
        float* __restrict__ out) {
    __shared__ float sw[H * 10];      // [k][m*2+j], 12 KB
    __shared__ float ex[4 * 128];     // gate exchange [m][j*64+b]
    __shared__ float cs[128];         // cell state [j*64+b]

    int tid = threadIdx.x;
    int b = tid & 63, m = tid >> 6;        // m in [0,5)
    int hh0 = blockIdx.x * 2;              // 2 hh per block

    // ---- stage this block's weight slice into smem (once) ----
    for (int idx = tid; idx < H * 10; idx += 320) {
        int k = idx / 10, r = idx - k * 10;
        int mm = r >> 1, j = r & 1;
        float v;
        if (mm < 4) {
            const float* Wx = (mm == 0) ? Wi : (mm == 1) ? Wf : (mm == 2) ? Wo : Wg;
            v = Wx[(300 + k) * H + hh0 + j];   // h rows of comb start at 300
        } else {
            v = g_WW[k * H + hh0 + j];
        }
        sw[idx] = v;
    }
    if (tid < 128) {
        int j = tid >> 6, bb = tid & 63;
        cs[tid] = g_cT[(hh0 + j) * B + bb];
    }
    __syncthreads();

    for (int t = 0; t < T; t++) {
        // gate warps (m<4) are dead at t==31; pred warp (m==4) is dead at t==0
        bool active = (m < 4) ? (t < 31) : (t > 0);
        float a0 = 0.f, a1 = 0.f;
        if (active) {
            if (m < 4) {
                int base = (t * 1200 + m * 300 + hh0) * B + b;
                a0 = g_baseT[base];
                a1 = g_baseT[base + B];
            } else {
                int base = ((t - 1) * H + hh0) * B + b;
                a0 = g_pbT[base];
                a1 = g_pbT[base + B];
            }
            // ---- dot over K=300: x via L1 (fresh buffer), weights from smem ----
            const float* xb = g_hS[t] + b;
            const float* wb = sw + m * 2;
#pragma unroll 10
            for (int k = 0; k < H; k++) {
                float x = __ldg(xb + k * B);
                float2 w = *(const float2*)(wb + k * 10);
                a0 = fmaf(x, w.x, a0);
                a1 = fmaf(x, w.y, a1);
            }
        }

        // ---- pred output (m==4) ----
        if (m == 4 && t > 0) {
            out[((size_t)b * T + t) * H + hh0 + 0] = a0;
            out[((size_t)b * T + t) * H + hh0 + 1] = a1;
        }

        if (t < 31) {
            // ---- exchange gate pre-acts, pointwise LSTM update ----
            if (m < 4) {
                ex[m * 128 + b]      = a0;
                ex[m * 128 + 64 + b] = a1;
            }
            __syncthreads();
            if (tid < 128) {
                int j = tid >> 6, bb = tid & 63;
                float ai = ex[tid];
                float af = ex[128 + tid];
                float ao = ex[256 + tid];
                float ag = ex[384 + tid];
                float iv = 1.f / (1.f + expf(-ai));
                float fv = 1.f / (1.f + expf(-af));
                float ov = 1.f / (1.f + expf(-ao));
                float gv = tanhf(ag);
                float cn = fv * cs[tid] + iv * gv;
                cs[tid] = cn;
                g_hS[t + 1][(hh0 + j) * B + bb] = ov * tanhf(cn);
            }
            // ---- grid barrier: all h writes visible before next step's reads ----
            __threadfence();
            __syncthreads();
            if (tid == 0) {
                atomicAdd(&g_cnt, 1u);
                unsigned target = (unsigned)NBLK * (unsigned)(t + 1);
                while (*((volatile unsigned*)&g_cnt) < target) { }
            }
            __syncthreads();
        }
    }
}

// ------------------- launch -------------------
extern "C" void kernel_launch(void* const* d_in, const int* in_sizes, int n_in,
                              void* d_out, int out_size) {
    const float* enc    = (const float*)d_in[0];
    const int*   caps   = (const int*)d_in[1];
    const float* emb    = (const float*)d_in[2];
    const float* Wh0    = (const float*)d_in[3];
    const float* bh0    = (const float*)d_in[4];
    const float* Wc0    = (const float*)d_in[5];
    const float* bc0    = (const float*)d_in[6];
    const float* We_enc = (const float*)d_in[7];
    // d_in[8] We_hid, d_in[9] be: unused — constant shifts inside softmax cancel.
    const float* Wi  = (const float*)d_in[10];
    const float* bi  = (const float*)d_in[11];
    const float* Wf  = (const float*)d_in[12];
    const float* bf  = (const float*)d_in[13];
    const float* Wo  = (const float*)d_in[14];
    const float* bo  = (const float*)d_in[15];
    const float* Wg  = (const float*)d_in[16];
    const float* bg  = (const float*)d_in[17];
    const float* Wcp = (const float*)d_in[18];
    const float* bcp = (const float*)d_in[19];
    const float* Whp = (const float*)d_in[20];
    const float* bhp = (const float*)d_in[21];
    const float* Wop = (const float*)d_in[22];
    const float* bop = (const float*)d_in[23];
    float* out = (float*)d_out;

    k_eenc<<<1600, 128>>>(enc, We_enc);
    k_softmax<<<64, 128>>>();
    k_meanctx<<<512, 256>>>(enc);
    k_h0c0<<<128, 320>>>(Wh0, bh0, Wc0, bc0);
    k_cw<<<75, 320>>>(Wi, Wf, Wo, Wg, Wcp);
    {
        dim3 gb(60, 31);
        k_base<<<gb, 320>>>(caps, emb, Wi, Wf, Wo, Wg, bi, bf, bo, bg);
    }
    k_sb<<<(31 * H * B + 255) / 256, 256>>>(caps, emb, bcp, bhp);
    {
        dim3 gp(15, 31);
        k_pbase<<<gp, 320>>>(Wop, bop);
    }
    k_ww<<<(H * H + 255) / 256, 256>>>(Whp, Wop);
    k_out0<<<(B * H + 255) / 256, 256>>>(emb, out);

    k_steps<<<NBLK, 320>>>(Wi, Wf, Wo, Wg, out);
}

// round 4
// speedup vs baseline: 3.4607x; 1.1460x over previous
#include <cuda_runtime.h>
#include <math.h>

#define B 64
#define Cc 100
#define Ff 2048
#define T 32
#define H 300
#define NBLK 148   // persistent step-kernel grid == SM count

typedef unsigned long long ull;

// packed f32x2 helpers (numerics identical to 2x fmaf)
__device__ __forceinline__ ull pk2(float x, float y) {
    ull r; asm("mov.b64 %0, {%1,%2};" : "=l"(r) : "f"(x), "f"(y)); return r;
}
__device__ __forceinline__ void fma2(ull& d, ull a, ull b) {
    asm("fma.rn.f32x2 %0, %1, %2, %3;" : "=l"(d) : "l"(a), "l"(b), "l"(d));
}
__device__ __forceinline__ float2 upk2(ull v) {
    float2 r; asm("mov.b64 {%0,%1}, %2;" : "=f"(r.x), "=f"(r.y) : "l"(v)); return r;
}

// ------------------- scratch (static device memory, no allocs) -------------------
__device__ float g_meanT[Ff * B];         // mean over C, transposed [f][b]
__device__ float g_eenc[B * Cc];          // enc @ We_enc
__device__ float g_attn[B * Cc];          // softmax(e_enc)  (time-invariant!)
__device__ float g_ctxT[Ff * B];          // ctx transposed [f][b]
__device__ float g_cT[H * B];             // cell state init [hh][b]
__device__ float g_hS[T][H * B];          // hidden state, FRESH buffer per step (L1-safe)
__device__ float g_CWT[1504 * B];         // ctx @ [Wi|Wf|Wo|Wg ctx-rows, Wcp], [j][b]
__device__ float g_baseT[31 * 1200 * B];  // per-step gate pre-act base [t][j][b]
__device__ float g_sbT[31 * H * B];       // sbase [t][k][b]
__device__ float g_pbT[31 * H * B];       // pbase = sbase@Wop + bop, [t][jj][b]
__device__ float g_WW[H * H];             // Whp @ Wop
__device__ unsigned g_cnt;                // grid-sync counter (reset each launch in k_ww)

// ------------------- prologue kernels -------------------

// one warp per (b,c) row: coalesced 512B/warp-load + shuffle reduce
__global__ void k_eenc(const float* __restrict__ enc, const float* __restrict__ We) {
    int w = blockIdx.x * 4 + (threadIdx.x >> 5);    // 1600 blocks x 128
    int lane = threadIdx.x & 31;
    if (w >= B * Cc) return;
    const float4* row = (const float4*)(enc + (size_t)w * Ff);
    const float4* wv = (const float4*)We;
    float s = 0.f;
#pragma unroll
    for (int i = 0; i < Ff / 4; i += 32) {
        float4 a = row[i + lane], c4 = wv[i + lane];
        s += a.x * c4.x + a.y * c4.y + a.z * c4.z + a.w * c4.w;
    }
#pragma unroll
    for (int o = 16; o > 0; o >>= 1) s += __shfl_down_sync(0xffffffffu, s, o);
    if (lane == 0) g_eenc[w] = s;
}

// softmax over C=100 per batch row. (h-dot and be are constant shifts -> dropped)
__global__ void k_softmax() {
    __shared__ float sv[128];
    int b = blockIdx.x, tid = threadIdx.x;
    float v = (tid < Cc) ? g_eenc[b * Cc + tid] : -1e30f;
    sv[tid] = v;
    __syncthreads();
    for (int s = 64; s > 0; s >>= 1) {
        if (tid < s) sv[tid] = fmaxf(sv[tid], sv[tid + s]);
        __syncthreads();
    }
    float mx = sv[0];
    __syncthreads();
    float e = (tid < Cc) ? expf(v - mx) : 0.f;
    sv[tid] = e;
    __syncthreads();
    for (int s = 64; s > 0; s >>= 1) {
        if (tid < s) sv[tid] += sv[tid + s];
        __syncthreads();
    }
    float inv = 1.0f / sv[0];
    if (tid < Cc) g_attn[b * Cc + tid] = e * inv;
}

// fused: ctx (attn-weighted sum over c) AND mean (uniform sum over c) in ONE 52MB scan
__global__ void k_meanctx(const float* __restrict__ enc) {
    __shared__ float at[Cc];
    int idx = blockIdx.x * 256 + threadIdx.x;       // 131072 threads, 8 blocks per b
    int b = idx >> 11, f = idx & 2047;
    if (threadIdx.x < Cc) at[threadIdx.x] = g_attn[b * Cc + threadIdx.x];
    __syncthreads();
    const float* p = enc + (size_t)b * Cc * Ff + f;
    float sc = 0.f, sm = 0.f;
#pragma unroll 4
    for (int c = 0; c < Cc; c++) {
        float v = p[c * Ff];
        sc = fmaf(at[c], v, sc);
        sm += v;
    }
    g_ctxT[f * B + b] = sc;
    g_meanT[f * B + b] = sm * (1.0f / Cc);
}

// h0/c0 as a 600-column GEMM over K=2048 (k_cw pattern).
// grid 120 x 320: jq picks 1 of 5 columns per block, b = lane group.
__global__ void k_h0c0(const float* __restrict__ Wh0, const float* __restrict__ bh0,
                       const float* __restrict__ Wc0, const float* __restrict__ bc0) {
    int tid = threadIdx.x;
    int b = tid & 63, jq = tid >> 6;
    int j = blockIdx.x * 5 + jq;         // 0..599
    const float* W; const float* bias; int col;
    if (j < 300) { W = Wh0; bias = bh0; col = j; }
    else         { W = Wc0; bias = bc0; col = j - 300; }
    float acc = bias[col];
    const float* xp = g_meanT + b;
    const float* wp = W + col;
#pragma unroll 8
    for (int f = 0; f < Ff; f++) acc = fmaf(xp[f * B], wp[f * H], acc);
    float v = tanhf(acc);
    if (j < 300) g_hS[0][j * B + b] = v;
    else         g_cT[col * B + b] = v;
}

// CWT[j][b] = sum_f ctx[b][f] * Wctx[f][j], j<1200: gate ctx-rows, 1200..1499: Wcp
__global__ void k_cw(const float* __restrict__ Wi, const float* __restrict__ Wf,
                     const float* __restrict__ Wo, const float* __restrict__ Wg,
                     const float* __restrict__ Wcp) {
    int tid = threadIdx.x;              // 320 threads: 5 j-quads x 64 b
    int b = tid & 63, jq = tid >> 6;
    int j0 = blockIdx.x * 20 + jq * 4;  // grid 75 -> j0 < 1500, j0 % 4 == 0
    const float* wbase;
    if (j0 < 1200) {
        int gate = j0 / 300, col = j0 - gate * 300;
        const float* Wx = (gate == 0) ? Wi : (gate == 1) ? Wf : (gate == 2) ? Wo : Wg;
        wbase = Wx + 600 * H + col;     // ctx rows start at comb row 600
    } else {
        wbase = Wcp + (j0 - 1200);
    }
    ull a01 = pk2(0.f, 0.f), a23 = pk2(0.f, 0.f);
    const float* xp = g_ctxT + b;
#pragma unroll 4
    for (int f = 0; f < Ff; f++) {
        float x = xp[f * B];
        ull xx = pk2(x, x);
        ulonglong2 w = *(const ulonglong2*)(wbase + f * H);
        fma2(a01, xx, w.x);
        fma2(a23, xx, w.y);
    }
    float2 r01 = upk2(a01), r23 = upk2(a23);
    g_CWT[(j0 + 0) * B + b] = r01.x; g_CWT[(j0 + 1) * B + b] = r01.y;
    g_CWT[(j0 + 2) * B + b] = r23.x; g_CWT[(j0 + 3) * B + b] = r23.y;
}

// baseT[t][j][b] = bias_g[col] + CWT[j][b] + emb[cap[b][t]] @ (gate emb-rows)
__global__ void k_base(const int* __restrict__ caps, const float* __restrict__ emb,
                       const float* __restrict__ Wi, const float* __restrict__ Wf,
                       const float* __restrict__ Wo, const float* __restrict__ Wg,
                       const float* __restrict__ bi, const float* __restrict__ bf,
                       const float* __restrict__ bo, const float* __restrict__ bg) {
    __shared__ float xs[64 * 61];
    __shared__ int cap_s[64];
    int tid = threadIdx.x;              // 320
    int t = blockIdx.y;
    int b = tid & 63, jq = tid >> 6;
    int j0 = blockIdx.x * 20 + jq * 4;  // grid.x=60 -> j0 < 1200
    int gate = j0 / 300, col0 = j0 - gate * 300;
    const float* Wx = (gate == 0) ? Wi : (gate == 1) ? Wf : (gate == 2) ? Wo : Wg;
    const float* bx = (gate == 0) ? bi : (gate == 1) ? bf : (gate == 2) ? bo : bg;
    if (tid < 64) cap_s[tid] = caps[tid * T + t];
    __syncthreads();
    ull a01 = pk2(bx[col0 + 0] + g_CWT[(j0 + 0) * B + b],
                  bx[col0 + 1] + g_CWT[(j0 + 1) * B + b]);
    ull a23 = pk2(bx[col0 + 2] + g_CWT[(j0 + 2) * B + b],
                  bx[col0 + 3] + g_CWT[(j0 + 3) * B + b]);
    for (int c0 = 0; c0 < H; c0 += 60) {
        __syncthreads();
        for (int i = tid; i < 64 * 60; i += 320) {
            int bb = i / 60, kk = i - bb * 60;
            xs[bb * 61 + kk] = emb[(size_t)cap_s[bb] * H + c0 + kk];
        }
        __syncthreads();
        const float* wrow = Wx + c0 * H + col0;
#pragma unroll 10
        for (int kk = 0; kk < 60; kk++) {
            float x = xs[b * 61 + kk];
            ull xx = pk2(x, x);
            ulonglong2 w = *(const ulonglong2*)(wrow + kk * H);
            fma2(a01, xx, w.x);
            fma2(a23, xx, w.y);
        }
    }
    float2 r01 = upk2(a01), r23 = upk2(a23);
    int base = t * 1200;
    g_baseT[(base + j0 + 0) * B + b] = r01.x;
    g_baseT[(base + j0 + 1) * B + b] = r01.y;
    g_baseT[(base + j0 + 2) * B + b] = r23.x;
    g_baseT[(base + j0 + 3) * B + b] = r23.y;
}

// sbT[t][k][b] = emb_t[b][k] + ctx@Wcp[k] + bcp[k] + bhp[k]
__global__ void k_sb(const int* __restrict__ caps, const float* __restrict__ emb,
                     const float* __restrict__ bcp, const float* __restrict__ bhp) {
    int idx = blockIdx.x * 256 + threadIdx.x;
    if (idx >= 31 * H * B) return;
    int b = idx & 63, r = idx >> 6;
    int k = r % H, t = r / H;
    int cap = caps[b * T + t];
    g_sbT[idx] = emb[(size_t)cap * H + k] + g_CWT[(1200 + k) * B + b] + bcp[k] + bhp[k];
}

// pbT[t][jj][b] = bop[jj] + sum_k sbT[t][k][b] * Wop[k][jj]
__global__ void k_pbase(const float* __restrict__ Wop, const float* __restrict__ bop) {
    int tid = threadIdx.x;              // 320
    int t = blockIdx.y;
    int b = tid & 63, jq = tid >> 6;
    int j0 = blockIdx.x * 20 + jq * 4;  // grid.x=15 -> j0 < 300
    ull a01 = pk2(bop[j0], bop[j0 + 1]);
    ull a23 = pk2(bop[j0 + 2], bop[j0 + 3]);
    const float* xp = g_sbT + t * H * B + b;
    const float* wrow = Wop + j0;
#pragma unroll 4
    for (int k = 0; k < H; k++) {
        float x = xp[k * B];
        ull xx = pk2(x, x);
        ulonglong2 w = *(const ulonglong2*)(wrow + k * H);
        fma2(a01, xx, w.x);
        fma2(a23, xx, w.y);
    }
    float2 r01 = upk2(a01), r23 = upk2(a23);
    int base = t * H;
    g_pbT[(base + j0 + 0) * B + b] = r01.x;
    g_pbT[(base + j0 + 1) * B + b] = r01.y;
    g_pbT[(base + j0 + 2) * B + b] = r23.x;
    g_pbT[(base + j0 + 3) * B + b] = r23.y;
}

// WW = Whp @ Wop  (300x300); also resets the grid-sync counter for this launch
__global__ void k_ww(const float* __restrict__ Whp, const float* __restrict__ Wop) {
    int idx = blockIdx.x * 256 + threadIdx.x;
    if (idx == 0) g_cnt = 0;
    if (idx >= H * H) return;
    int k = idx / H, jj = idx - k * H;
    float s = 0.f;
    const float* a = Whp + k * H;
    const float* w = Wop + jj;
#pragma unroll 4
    for (int m = 0; m < H; m++) s += a[m] * w[m * H];
    g_WW[idx] = s;
}

__global__ void k_out0(const float* __restrict__ emb, float* __restrict__ out) {
    int idx = blockIdx.x * 256 + threadIdx.x;
    if (idx >= B * H) return;
    int b = idx / H, jj = idx - b * H;
    out[(size_t)b * T * H + jj] = emb[1 * H + jj];   // BOS = 1
}

// ------------------- persistent recurrence kernel (ONE launch, 32 steps) -------------------
// 148 blocks (== SM count, one per SM) x 320 threads. Blocks 0..3 own 3 hh cols,
// blocks 4..147 own 2. Weights in SMEM once. Each step: h chunk-staged into SMEM
// (bulk coalesced float4 -> massive MLP), then an FFMA2 dot entirely out of SMEM.
__global__ void __launch_bounds__(320, 1) k_steps(
        const float* __restrict__ Wi, const float* __restrict__ Wf,
        const float* __restrict__ Wo, const float* __restrict__ Wg,
        float* __restrict__ out) {
    __shared__ float sw[5 * 300 * 4];   // [m][k][4 cols padded], 24 KB
    __shared__ float4 xs4[1600];        // one 100-k chunk of h: [kk][b], 25.6 KB
    __shared__ float ex[4 * 192];       // gate exchange [gate][c*64+b]
    __shared__ float cs[192];           // cell state [c*64+b]

    int tid = threadIdx.x;
    int b = tid & 63, m = tid >> 6;          // m in [0,5)
    int bid = blockIdx.x;
    int nc  = (bid < 4) ? 3 : 2;
    int hh0 = (bid < 4) ? bid * 3 : 12 + (bid - 4) * 2;

    // ---- stage this block's weight slice into smem (once) ----
    for (int i = tid; i < 5 * 300 * 3; i += 320) {
        int c = i % 3, r = i / 3;
        int k = r % 300, mm = r / 300;
        if (c < nc) {
            float v;
            if (mm < 4) {
                const float* Wx = (mm == 0) ? Wi : (mm == 1) ? Wf : (mm == 2) ? Wo : Wg;
                v = Wx[(300 + k) * H + hh0 + c];   // h rows of comb start at 300
            } else {
                v = g_WW[k * H + hh0 + c];
            }
            sw[(mm * 300 + k) * 4 + c] = v;
        }
    }
    if (tid < nc * 64) {
        cs[tid] = g_cT[(hh0 + (tid >> 6)) * B + (tid & 63)];
    }
    __syncthreads();

    for (int t = 0; t < T; t++) {
        bool gatew = (m < 4);
        bool act = gatew ? (t < 31) : (t > 0);
        ull a01 = pk2(0.f, 0.f);
        float a2 = 0.f;
        if (act) {
            if (gatew) {
                int base = (t * 1200 + m * 300 + hh0) * B + b;
                a01 = pk2(g_baseT[base], g_baseT[base + B]);
                if (nc == 3) a2 = g_baseT[base + 2 * B];
            } else {
                int base = ((t - 1) * H + hh0) * B + b;
                a01 = pk2(g_pbT[base], g_pbT[base + B]);
                if (nc == 3) a2 = g_pbT[base + 2 * B];
            }
        }
        // ---- 3 chunks of 100 k: bulk-stage h into smem, dot from smem ----
        const float4* hsrc = (const float4*)g_hS[t];
        for (int ch = 0; ch < 3; ch++) {
            __syncthreads();
#pragma unroll
            for (int j = 0; j < 5; j++)
                xs4[tid + j * 320] = hsrc[ch * 1600 + tid + j * 320];
            __syncthreads();
            if (act) {
                const float* xc = ((const float*)xs4) + b;
                const float* swp = sw + (m * 300 + ch * 100) * 4;
                if (nc == 2) {
#pragma unroll 10
                    for (int kk = 0; kk < 100; kk++) {
                        float x = xc[kk * 64];
                        ull xx = pk2(x, x);
                        ull w = *(const ull*)(swp + kk * 4);
                        fma2(a01, xx, w);
                    }
                } else {
#pragma unroll 10
                    for (int kk = 0; kk < 100; kk++) {
                        float x = xc[kk * 64];
                        ull xx = pk2(x, x);
                        ull w = *(const ull*)(swp + kk * 4);
                        fma2(a01, xx, w);
                        a2 = fmaf(x, swp[kk * 4 + 2], a2);
                    }
                }
            }
        }
        float2 a = upk2(a01);

        // ---- pred output (m==4) ----
        if (!gatew && t > 0) {
            size_t o = ((size_t)b * T + t) * H + hh0;
            out[o] = a.x; out[o + 1] = a.y;
            if (nc == 3) out[o + 2] = a2;
        }

        if (t < 31) {
            // ---- exchange gate pre-acts, pointwise LSTM update ----
            if (gatew) {
                ex[m * 192 + b]       = a.x;
                ex[m * 192 + 64 + b]  = a.y;
                if (nc == 3) ex[m * 192 + 128 + b] = a2;
            }
            __syncthreads();
            if (tid < nc * 64) {
                float ai = ex[tid];
                float af = ex[192 + tid];
                float ao = ex[384 + tid];
                float ag = ex[576 + tid];
                float iv = 1.f / (1.f + expf(-ai));
                float fv = 1.f / (1.f + expf(-af));
                float ov = 1.f / (1.f + expf(-ao));
                float gv = tanhf(ag);
                float cn = fv * cs[tid] + iv * gv;
                cs[tid] = cn;
                g_hS[t + 1][(hh0 + (tid >> 6)) * B + (tid & 63)] = ov * tanhf(cn);
            }
            // ---- grid barrier: all h writes visible before next step's reads ----
            __threadfence();
            __syncthreads();
            if (tid == 0) {
                atomicAdd(&g_cnt, 1u);
                unsigned target = (unsigned)NBLK * (unsigned)(t + 1);
                while (*((volatile unsigned*)&g_cnt) < target) { }
            }
            __syncthreads();
        }
    }
}

// ------------------- launch -------------------
extern "C" void kernel_launch(void* const* d_in, const int* in_sizes, int n_in,
                              void* d_out, int out_size) {
    const float* enc    = (const float*)d_in[0];
    const int*   caps   = (const int*)d_in[1];
    const float* emb    = (const float*)d_in[2];
    const float* Wh0    = (const float*)d_in[3];
    const float* bh0    = (const float*)d_in[4];
    const float* Wc0    = (const float*)d_in[5];
    const float* bc0    = (const float*)d_in[6];
    const float* We_enc = (const float*)d_in[7];
    // d_in[8] We_hid, d_in[9] be: unused — constant shifts inside softmax cancel.
    const float* Wi  = (const float*)d_in[10];
    const float* bi  = (const float*)d_in[11];
    const float* Wf  = (const float*)d_in[12];
    const float* bf  = (const float*)d_in[13];
    const float* Wo  = (const float*)d_in[14];
    const float* bo  = (const float*)d_in[15];
    const float* Wg  = (const float*)d_in[16];
    const float* bg  = (const float*)d_in[17];
    const float* Wcp = (const float*)d_in[18];
    const float* bcp = (const float*)d_in[19];
    const float* Whp = (const float*)d_in[20];
    const float* bhp = (const float*)d_in[21];
    const float* Wop = (const float*)d_in[22];
    const float* bop = (const float*)d_in[23];
    float* out = (float*)d_out;

    k_eenc<<<1600, 128>>>(enc, We_enc);
    k_softmax<<<64, 128>>>();
    k_meanctx<<<512, 256>>>(enc);
    k_h0c0<<<120, 320>>>(Wh0, bh0, Wc0, bc0);
    k_cw<<<75, 320>>>(Wi, Wf, Wo, Wg, Wcp);
    {
        dim3 gb(60, 31);
        k_base<<<gb, 320>>>(caps, emb, Wi, Wf, Wo, Wg, bi, bf, bo, bg);
    }
    k_sb<<<(31 * H * B + 255) / 256, 256>>>(caps, emb, bcp, bhp);
    {
        dim3 gp(15, 31);
        k_pbase<<<gp, 320>>>(Wop, bop);
    }
    k_ww<<<(H * H + 255) / 256, 256>>>(Whp, Wop);
    k_out0<<<(B * H + 255) / 256, 256>>>(emb, out);

    k_steps<<<NBLK, 320>>>(Wi, Wf, Wo, Wg, out);
}

// round 5
// speedup vs baseline: 5.9863x; 1.7298x over previous
#include <cuda_runtime.h>
#include <math.h>

#define B 64
#define Cc 100
#define Ff 2048
#define T 32
#define H 300
#define NBLK 148   // persistent step-kernel grid == SM count

typedef unsigned long long ull;

// packed f32x2 helpers (numerics identical to 2x fmaf)
__device__ __forceinline__ ull pk2(float x, float y) {
    ull r; asm("mov.b64 %0, {%1,%2};" : "=l"(r) : "f"(x), "f"(y)); return r;
}
__device__ __forceinline__ void fma2(ull& d, ull a, ull b) {
    asm("fma.rn.f32x2 %0, %1, %2, %3;" : "=l"(d) : "l"(a), "l"(b), "l"(d));
}
__device__ __forceinline__ float2 upk2(ull v) {
    float2 r; asm("mov.b64 {%0,%1}, %2;" : "=f"(r.x), "=f"(r.y) : "l"(v)); return r;
}

// ------------------- scratch (static device memory, no allocs) -------------------
__device__ float g_meanT[Ff * B];         // mean over C, transposed [f][b]
__device__ float g_eenc[B * Cc];          // enc @ We_enc
__device__ float g_attn[B * Cc];          // softmax(e_enc)  (time-invariant!)
__device__ float g_ctxT[Ff * B];          // ctx transposed [f][b]
__device__ float g_cT[H * B];             // cell state init [hh][b]
__device__ float g_hS[T][H * B];          // hidden state, FRESH buffer per step (L1-safe)
__device__ float g_CWT[1504 * B];         // ctx @ [Wi|Wf|Wo|Wg ctx-rows, Wcp], [j][b]
__device__ float g_baseT[31 * 1200 * B];  // per-step gate pre-act base [t][j][b]
__device__ float g_sbT[31 * H * B];       // sbase [t][k][b]
__device__ float g_pbT[31 * H * B];       // pbase = sbase@Wop + bop, [t][jj][b]
__device__ float g_WW[H * H];             // Whp @ Wop
__device__ unsigned g_cnt;                // grid-sync counter (reset each launch in k_ww)

// ------------------- prologue kernels -------------------

// one warp per (b,c) row: coalesced 512B/warp-load + shuffle reduce
__global__ void k_eenc(const float* __restrict__ enc, const float* __restrict__ We) {
    int w = blockIdx.x * 4 + (threadIdx.x >> 5);    // 1600 blocks x 128
    int lane = threadIdx.x & 31;
    if (w >= B * Cc) return;
    const float4* row = (const float4*)(enc + (size_t)w * Ff);
    const float4* wv = (const float4*)We;
    float s = 0.f;
#pragma unroll
    for (int i = 0; i < Ff / 4; i += 32) {
        float4 a = row[i + lane], c4 = wv[i + lane];
        s += a.x * c4.x + a.y * c4.y + a.z * c4.z + a.w * c4.w;
    }
#pragma unroll
    for (int o = 16; o > 0; o >>= 1) s += __shfl_down_sync(0xffffffffu, s, o);
    if (lane == 0) g_eenc[w] = s;
}

// softmax over C=100 per batch row. (h-dot and be are constant shifts -> dropped)
__global__ void k_softmax() {
    __shared__ float sv[128];
    int b = blockIdx.x, tid = threadIdx.x;
    float v = (tid < Cc) ? g_eenc[b * Cc + tid] : -1e30f;
    sv[tid] = v;
    __syncthreads();
    for (int s = 64; s > 0; s >>= 1) {
        if (tid < s) sv[tid] = fmaxf(sv[tid], sv[tid + s]);
        __syncthreads();
    }
    float mx = sv[0];
    __syncthreads();
    float e = (tid < Cc) ? expf(v - mx) : 0.f;
    sv[tid] = e;
    __syncthreads();
    for (int s = 64; s > 0; s >>= 1) {
        if (tid < s) sv[tid] += sv[tid + s];
        __syncthreads();
    }
    float inv = 1.0f / sv[0];
    if (tid < Cc) g_attn[b * Cc + tid] = e * inv;
}

// fused: ctx (attn-weighted sum over c) AND mean (uniform sum over c) in ONE 52MB scan
__global__ void k_meanctx(const float* __restrict__ enc) {
    __shared__ float at[Cc];
    int idx = blockIdx.x * 256 + threadIdx.x;       // 131072 threads, 8 blocks per b
    int b = idx >> 11, f = idx & 2047;
    if (threadIdx.x < Cc) at[threadIdx.x] = g_attn[b * Cc + threadIdx.x];
    __syncthreads();
    const float* p = enc + (size_t)b * Cc * Ff + f;
    float sc = 0.f, sm = 0.f;
#pragma unroll 4
    for (int c = 0; c < Cc; c++) {
        float v = p[c * Ff];
        sc = fmaf(at[c], v, sc);
        sm += v;
    }
    g_ctxT[f * B + b] = sc;
    g_meanT[f * B + b] = sm * (1.0f / Cc);
}

// h0/c0: 600-col GEMM over K=2048, BOTH operands chunk-staged in smem.
// grid 120 x 320: blocks 0..59 -> Wh0, 60..119 -> Wc0; 5 cols per block.
__global__ void k_h0c0(const float* __restrict__ Wh0, const float* __restrict__ bh0,
                       const float* __restrict__ Wc0, const float* __restrict__ bc0) {
    __shared__ float4 xs4[128 * 16];    // 128 k x 64 b = 32 KB
    __shared__ float ws[128 * 5];       // 128 k x 5 cols
    int tid = threadIdx.x;
    int b = tid & 63, jq = tid >> 6;
    bool isC = blockIdx.x >= 60;
    int colbase = (isC ? (blockIdx.x - 60) : blockIdx.x) * 5;
    const float* W = isC ? Wc0 : Wh0;
    const float* bias = isC ? bc0 : bh0;
    float acc = 0.f;
    for (int c0 = 0; c0 < Ff; c0 += 128) {
        __syncthreads();
        const float4* xsrc = (const float4*)(g_meanT + c0 * B);
        for (int i = tid; i < 128 * 16; i += 320) xs4[i] = xsrc[i];
        for (int i = tid; i < 128 * 5; i += 320) {
            int kk = i / 5, c = i - kk * 5;
            ws[i] = W[(size_t)(c0 + kk) * H + colbase + c];
        }
        __syncthreads();
        const float* xc = ((const float*)xs4) + b;
#pragma unroll 8
        for (int kk = 0; kk < 128; kk++)
            acc = fmaf(xc[kk * 64], ws[kk * 5 + jq], acc);
    }
    int col = colbase + jq;
    float v = tanhf(acc + bias[col]);
    if (isC) g_cT[col * B + b] = v;
    else     g_hS[0][col * B + b] = v;
}

// CWT[j][b] = sum_f ctx[b][f] * Wctx[f][j]; grid 150, 10 cols/block (2 per thread).
// j<1200: gate ctx-rows, 1200..1499: Wcp. Both operands chunk-staged.
__global__ void k_cw(const float* __restrict__ Wi, const float* __restrict__ Wf,
                     const float* __restrict__ Wo, const float* __restrict__ Wg,
                     const float* __restrict__ Wcp) {
    __shared__ float4 xs4[128 * 16];    // 32 KB
    __shared__ float ws[128 * 10];      // 5 KB
    int tid = threadIdx.x;
    int b = tid & 63, jq = tid >> 6;
    int j0 = blockIdx.x * 10;           // gate boundaries are multiples of 10
    const float* wbase;
    if (j0 < 1200) {
        int gate = j0 / 300, col = j0 - gate * 300;
        const float* Wx = (gate == 0) ? Wi : (gate == 1) ? Wf : (gate == 2) ? Wo : Wg;
        wbase = Wx + 600 * H + col;     // ctx rows start at comb row 600
    } else {
        wbase = Wcp + (j0 - 1200);
    }
    ull a01 = pk2(0.f, 0.f);
    for (int c0 = 0; c0 < Ff; c0 += 128) {
        __syncthreads();
        const float4* xsrc = (const float4*)(g_ctxT + c0 * B);
        for (int i = tid; i < 128 * 16; i += 320) xs4[i] = xsrc[i];
        for (int i = tid; i < 128 * 10; i += 320) {
            int kk = i / 10, c = i - kk * 10;
            ws[i] = wbase[(size_t)(c0 + kk) * H + c];
        }
        __syncthreads();
        const float* xc = ((const float*)xs4) + b;
        const float* wp = ws + jq * 2;
#pragma unroll 8
        for (int kk = 0; kk < 128; kk++) {
            float x = xc[kk * 64];
            fma2(a01, pk2(x, x), *(const ull*)(wp + kk * 10));
        }
    }
    float2 r = upk2(a01);
    int j = j0 + jq * 2;
    g_CWT[(j + 0) * B + b] = r.x;
    g_CWT[(j + 1) * B + b] = r.y;
}

// baseT[t][j][b] = bias_g[col] + CWT[j][b] + emb[cap[b][t]] @ (gate emb-rows)
// weight tile (300 x 20) staged in smem ONCE per block; x staged per 60-k chunk.
__global__ void k_base(const int* __restrict__ caps, const float* __restrict__ emb,
                       const float* __restrict__ Wi, const float* __restrict__ Wf,
                       const float* __restrict__ Wo, const float* __restrict__ Wg,
                       const float* __restrict__ bi, const float* __restrict__ bf,
                       const float* __restrict__ bo, const float* __restrict__ bg) {
    __shared__ float xs[64 * 61];
    __shared__ float ws[300 * 20];      // 24 KB
    __shared__ int cap_s[64];
    int tid = threadIdx.x;              // 320
    int t = blockIdx.y;
    int b = tid & 63, jq = tid >> 6;
    int jB = blockIdx.x * 20;           // block col base; gate boundaries mult of 20
    int gate = jB / 300, colB = jB - gate * 300;
    int j0 = jB + jq * 4;
    int col0 = colB + jq * 4;
    const float* Wx = (gate == 0) ? Wi : (gate == 1) ? Wf : (gate == 2) ? Wo : Wg;
    const float* bx = (gate == 0) ? bi : (gate == 1) ? bf : (gate == 2) ? bo : bg;
    if (tid < 64) cap_s[tid] = caps[tid * T + t];
    // stage full weight tile (coalesced 80B rows, entire tile in flight)
    for (int i = tid; i < 300 * 20; i += 320) {
        int kk = i / 20, c = i - kk * 20;
        ws[i] = Wx[(size_t)kk * H + colB + c];
    }
    __syncthreads();
    ull a01 = pk2(bx[col0 + 0] + g_CWT[(j0 + 0) * B + b],
                  bx[col0 + 1] + g_CWT[(j0 + 1) * B + b]);
    ull a23 = pk2(bx[col0 + 2] + g_CWT[(j0 + 2) * B + b],
                  bx[col0 + 3] + g_CWT[(j0 + 3) * B + b]);
    for (int c0 = 0; c0 < H; c0 += 60) {
        __syncthreads();
        for (int i = tid; i < 64 * 60; i += 320) {
            int bb = i / 60, kk = i - bb * 60;
            xs[bb * 61 + kk] = emb[(size_t)cap_s[bb] * H + c0 + kk];
        }
        __syncthreads();
        const float* wp = ws + c0 * 20 + jq * 4;
#pragma unroll 10
        for (int kk = 0; kk < 60; kk++) {
            float x = xs[b * 61 + kk];
            ull xx = pk2(x, x);
            ulonglong2 w = *(const ulonglong2*)(wp + kk * 20);
            fma2(a01, xx, w.x);
            fma2(a23, xx, w.y);
        }
    }
    float2 r01 = upk2(a01), r23 = upk2(a23);
    int base = t * 1200;
    g_baseT[(base + j0 + 0) * B + b] = r01.x;
    g_baseT[(base + j0 + 1) * B + b] = r01.y;
    g_baseT[(base + j0 + 2) * B + b] = r23.x;
    g_baseT[(base + j0 + 3) * B + b] = r23.y;
}

// sbT[t][k][b] = emb_t[b][k] + ctx@Wcp[k] + bcp[k] + bhp[k]
__global__ void k_sb(const int* __restrict__ caps, const float* __restrict__ emb,
                     const float* __restrict__ bcp, const float* __restrict__ bhp) {
    int idx = blockIdx.x * 256 + threadIdx.x;
    if (idx >= 31 * H * B) return;
    int b = idx & 63, r = idx >> 6;
    int k = r % H, t = r / H;
    int cap = caps[b * T + t];
    g_sbT[idx] = emb[(size_t)cap * H + k] + g_CWT[(1200 + k) * B + b] + bcp[k] + bhp[k];
}

// pbT[t][jj][b] = bop[jj] + sum_k sbT[t][k][b] * Wop[k][jj]; w tile staged in smem
__global__ void k_pbase(const float* __restrict__ Wop, const float* __restrict__ bop) {
    __shared__ float ws[300 * 20];      // 24 KB
    int tid = threadIdx.x;              // 320
    int t = blockIdx.y;
    int b = tid & 63, jq = tid >> 6;
    int jB = blockIdx.x * 20;
    int j0 = jB + jq * 4;               // grid.x=15 -> j0 < 300
    for (int i = tid; i < 300 * 20; i += 320) {
        int kk = i / 20, c = i - kk * 20;
        ws[i] = Wop[(size_t)kk * H + jB + c];
    }
    __syncthreads();
    ull a01 = pk2(bop[j0], bop[j0 + 1]);
    ull a23 = pk2(bop[j0 + 2], bop[j0 + 3]);
    const float* xp = g_sbT + t * H * B + b;
    const float* wp = ws + jq * 4;
#pragma unroll 10
    for (int k = 0; k < H; k++) {
        float x = xp[k * B];
        ull xx = pk2(x, x);
        ulonglong2 w = *(const ulonglong2*)(wp + k * 20);
        fma2(a01, xx, w.x);
        fma2(a23, xx, w.y);
    }
    float2 r01 = upk2(a01), r23 = upk2(a23);
    int base = t * H;
    g_pbT[(base + j0 + 0) * B + b] = r01.x;
    g_pbT[(base + j0 + 1) * B + b] = r01.y;
    g_pbT[(base + j0 + 2) * B + b] = r23.x;
    g_pbT[(base + j0 + 3) * B + b] = r23.y;
}

// WW = Whp @ Wop  (300x300); also resets the grid-sync counter for this launch
__global__ void k_ww(const float* __restrict__ Whp, const float* __restrict__ Wop) {
    int idx = blockIdx.x * 256 + threadIdx.x;
    if (idx == 0) g_cnt = 0;
    if (idx >= H * H) return;
    int k = idx / H, jj = idx - k * H;
    float s = 0.f;
    const float* a = Whp + k * H;
    const float* w = Wop + jj;
#pragma unroll 4
    for (int m = 0; m < H; m++) s += a[m] * w[m * H];
    g_WW[idx] = s;
}

__global__ void k_out0(const float* __restrict__ emb, float* __restrict__ out) {
    int idx = blockIdx.x * 256 + threadIdx.x;
    if (idx >= B * H) return;
    int b = idx / H, jj = idx - b * H;
    out[(size_t)b * T * H + jj] = emb[1 * H + jj];   // BOS = 1
}

// ------------------- persistent recurrence kernel (ONE launch, 32 steps) -------------------
// 148 blocks (== SM count, one per SM) x 320 threads. Blocks 0..3 own 3 hh cols,
// blocks 4..147 own 2. Weights in SMEM once. Each step: h chunk-staged into SMEM
// (bulk coalesced float4 -> massive MLP), then an FFMA2 dot entirely out of SMEM.
__global__ void __launch_bounds__(320, 1) k_steps(
        const float* __restrict__ Wi, const float* __restrict__ Wf,
        const float* __restrict__ Wo, const float* __restrict__ Wg,
        float* __restrict__ out) {
    __shared__ float sw[5 * 300 * 4];   // [m][k][4 cols padded], 24 KB
    __shared__ float4 xs4[1600];        // one 100-k chunk of h: [kk][b], 25.6 KB
    __shared__ float ex[4 * 192];       // gate exchange [gate][c*64+b]
    __shared__ float cs[192];           // cell state [c*64+b]

    int tid = threadIdx.x;
    int b = tid & 63, m = tid >> 6;          // m in [0,5)
    int bid = blockIdx.x;
    int nc  = (bid < 4) ? 3 : 2;
    int hh0 = (bid < 4) ? bid * 3 : 12 + (bid - 4) * 2;

    // ---- stage this block's weight slice into smem (once) ----
    for (int i = tid; i < 5 * 300 * 3; i += 320) {
        int c = i % 3, r = i / 3;
        int k = r % 300, mm = r / 300;
        if (c < nc) {
            float v;
            if (mm < 4) {
                const float* Wx = (mm == 0) ? Wi : (mm == 1) ? Wf : (mm == 2) ? Wo : Wg;
                v = Wx[(300 + k) * H + hh0 + c];   // h rows of comb start at 300
            } else {
                v = g_WW[k * H + hh0 + c];
            }
            sw[(mm * 300 + k) * 4 + c] = v;
        }
    }
    if (tid < nc * 64) {
        cs[tid] = g_cT[(hh0 + (tid >> 6)) * B + (tid & 63)];
    }
    __syncthreads();

    for (int t = 0; t < T; t++) {
        bool gatew = (m < 4);
        bool act = gatew ? (t < 31) : (t > 0);
        ull a01 = pk2(0.f, 0.f);
        float a2 = 0.f;
        if (act) {
            if (gatew) {
                int base = (t * 1200 + m * 300 + hh0) * B + b;
                a01 = pk2(g_baseT[base], g_baseT[base + B]);
                if (nc == 3) a2 = g_baseT[base + 2 * B];
            } else {
                int base = ((t - 1) * H + hh0) * B + b;
                a01 = pk2(g_pbT[base], g_pbT[base + B]);
                if (nc == 3) a2 = g_pbT[base + 2 * B];
            }
        }
        // ---- 3 chunks of 100 k: bulk-stage h into smem, dot from smem ----
        const float4* hsrc = (const float4*)g_hS[t];
        for (int ch = 0; ch < 3; ch++) {
            __syncthreads();
#pragma unroll
            for (int j = 0; j < 5; j++)
                xs4[tid + j * 320] = hsrc[ch * 1600 + tid + j * 320];
            __syncthreads();
            if (act) {
                const float* xc = ((const float*)xs4) + b;
                const float* swp = sw + (m * 300 + ch * 100) * 4;
                if (nc == 2) {
#pragma unroll 10
                    for (int kk = 0; kk < 100; kk++) {
                        float x = xc[kk * 64];
                        ull xx = pk2(x, x);
                        ull w = *(const ull*)(swp + kk * 4);
                        fma2(a01, xx, w);
                    }
                } else {
#pragma unroll 10
                    for (int kk = 0; kk < 100; kk++) {
                        float x = xc[kk * 64];
                        ull xx = pk2(x, x);
                        ull w = *(const ull*)(swp + kk * 4);
                        fma2(a01, xx, w);
                        a2 = fmaf(x, swp[kk * 4 + 2], a2);
                    }
                }
            }
        }
        float2 a = upk2(a01);

        // ---- pred output (m==4) ----
        if (!gatew && t > 0) {
            size_t o = ((size_t)b * T + t) * H + hh0;
            out[o] = a.x; out[o + 1] = a.y;
            if (nc == 3) out[o + 2] = a2;
        }

        if (t < 31) {
            // ---- exchange gate pre-acts, pointwise LSTM update ----
            if (gatew) {
                ex[m * 192 + b]       = a.x;
                ex[m * 192 + 64 + b]  = a.y;
                if (nc == 3) ex[m * 192 + 128 + b] = a2;
            }
            __syncthreads();
            if (tid < nc * 64) {
                float ai = ex[tid];
                float af = ex[192 + tid];
                float ao = ex[384 + tid];
                float ag = ex[576 + tid];
                float iv = 1.f / (1.f + expf(-ai));
                float fv = 1.f / (1.f + expf(-af));
                float ov = 1.f / (1.f + expf(-ao));
                float gv = tanhf(ag);
                float cn = fv * cs[tid] + iv * gv;
                cs[tid] = cn;
                g_hS[t + 1][(hh0 + (tid >> 6)) * B + (tid & 63)] = ov * tanhf(cn);
            }
            // ---- grid barrier: all h writes visible before next step's reads ----
            __threadfence();
            __syncthreads();
            if (tid == 0) {
                atomicAdd(&g_cnt, 1u);
                unsigned target = (unsigned)NBLK * (unsigned)(t + 1);
                while (*((volatile unsigned*)&g_cnt) < target) { }
            }
            __syncthreads();
        }
    }
}

// ------------------- launch -------------------
extern "C" void kernel_launch(void* const* d_in, const int* in_sizes, int n_in,
                              void* d_out, int out_size) {
    const float* enc    = (const float*)d_in[0];
    const int*   caps   = (const int*)d_in[1];
    const float* emb    = (const float*)d_in[2];
    const float* Wh0    = (const float*)d_in[3];
    const float* bh0    = (const float*)d_in[4];
    const float* Wc0    = (const float*)d_in[5];
    const float* bc0    = (const float*)d_in[6];
    const float* We_enc = (const float*)d_in[7];
    // d_in[8] We_hid, d_in[9] be: unused — constant shifts inside softmax cancel.
    const float* Wi  = (const float*)d_in[10];
    const float* bi  = (const float*)d_in[11];
    const float* Wf  = (const float*)d_in[12];
    const float* bf  = (const float*)d_in[13];
    const float* Wo  = (const float*)d_in[14];
    const float* bo  = (const float*)d_in[15];
    const float* Wg  = (const float*)d_in[16];
    const float* bg  = (const float*)d_in[17];
    const float* Wcp = (const float*)d_in[18];
    const float* bcp = (const float*)d_in[19];
    const float* Whp = (const float*)d_in[20];
    const float* bhp = (const float*)d_in[21];
    const float* Wop = (const float*)d_in[22];
    const float* bop = (const float*)d_in[23];
    float* out = (float*)d_out;

    k_eenc<<<1600, 128>>>(enc, We_enc);
    k_softmax<<<64, 128>>>();
    k_meanctx<<<512, 256>>>(enc);
    k_h0c0<<<120, 320>>>(Wh0, bh0, Wc0, bc0);
    k_cw<<<150, 320>>>(Wi, Wf, Wo, Wg, Wcp);
    {
        dim3 gb(60, 31);
        k_base<<<gb, 320>>>(caps, emb, Wi, Wf, Wo, Wg, bi, bf, bo, bg);
    }
    k_sb<<<(31 * H * B + 255) / 256, 256>>>(caps, emb, bcp, bhp);
    {
        dim3 gp(15, 31);
        k_pbase<<<gp, 320>>>(Wop, bop);
    }
    k_ww<<<(H * H + 255) / 256, 256>>>(Whp, Wop);
    k_out0<<<(B * H + 255) / 256, 256>>>(emb, out);

    k_steps<<<NBLK, 320>>>(Wi, Wf, Wo, Wg, out);
}

// round 6
// speedup vs baseline: 7.3317x; 1.2247x over previous
#include <cuda_runtime.h>
#include <math.h>

#define B 64
#define Cc 100
#define Ff 2048
#define T 32
#define H 300
#define NBLK 148   // persistent step-kernel grid == SM count
#define HB_PITCH 304          // g_hB row pitch (floats), 16B-aligned rows
#define STEP_SMEM 98640       // k_steps dynamic smem bytes

typedef unsigned long long ull;

// packed f32x2 helpers (numerics identical to 2x fmaf)
__device__ __forceinline__ ull pk2(float x, float y) {
    ull r; asm("mov.b64 %0, {%1,%2};" : "=l"(r) : "f"(x), "f"(y)); return r;
}
__device__ __forceinline__ void fma2(ull& d, ull a, ull b) {
    asm("fma.rn.f32x2 %0, %1, %2, %3;" : "=l"(d) : "l"(a), "l"(b), "l"(d));
}
__device__ __forceinline__ float2 upk2(ull v) {
    float2 r; asm("mov.b64 {%0,%1}, %2;" : "=f"(r.x), "=f"(r.y) : "l"(v)); return r;
}

// ------------------- scratch (static device memory, no allocs) -------------------
__device__ float g_meanT[Ff * B];         // mean over C, transposed [f][b]
__device__ float g_eenc[B * Cc];          // enc @ We_enc
__device__ float g_attn[B * Cc];          // softmax(e_enc)  (time-invariant!)
__device__ float g_ctxT[Ff * B];          // ctx transposed [f][b]
__device__ float g_cT[H * B];             // cell state init [hh][b]
__device__ float g_hB[T * 64 * HB_PITCH]; // hidden state [t][b][k], fresh rows per step
__device__ float g_CWT[1504 * B];         // ctx @ [Wi|Wf|Wo|Wg ctx-rows, Wcp], [j][b]
__device__ float g_baseT[31 * 1200 * B];  // per-step gate pre-act base [t][j][b]
__device__ float g_sbT[31 * H * B];       // sbase [t][k][b]
__device__ float g_pbT[31 * H * B];       // pbase = sbase@Wop + bop, [t][jj][b]
__device__ float g_WW[H * H];             // Whp @ Wop
__device__ float g_p0[4 * 600 * B];       // h0c0 k-split partials
__device__ float g_pcw[2 * 1500 * B];     // cw k-split partials
__device__ unsigned g_cnt;                // grid-sync counter (reset each launch in k_ww)

// ------------------- prologue kernels -------------------

// one warp per (b,c) row: coalesced 512B/warp-load + shuffle reduce
__global__ void k_eenc(const float* __restrict__ enc, const float* __restrict__ We) {
    int w = blockIdx.x * 4 + (threadIdx.x >> 5);    // 1600 blocks x 128
    int lane = threadIdx.x & 31;
    if (w >= B * Cc) return;
    const float4* row = (const float4*)(enc + (size_t)w * Ff);
    const float4* wv = (const float4*)We;
    float s = 0.f;
#pragma unroll
    for (int i = 0; i < Ff / 4; i += 32) {
        float4 a = row[i + lane], c4 = wv[i + lane];
        s += a.x * c4.x + a.y * c4.y + a.z * c4.z + a.w * c4.w;
    }
#pragma unroll
    for (int o = 16; o > 0; o >>= 1) s += __shfl_down_sync(0xffffffffu, s, o);
    if (lane == 0) g_eenc[w] = s;
}

// softmax over C=100 per batch row. (h-dot and be are constant shifts -> dropped)
__global__ void k_softmax() {
    __shared__ float sv[128];
    int b = blockIdx.x, tid = threadIdx.x;
    float v = (tid < Cc) ? g_eenc[b * Cc + tid] : -1e30f;
    sv[tid] = v;
    __syncthreads();
    for (int s = 64; s > 0; s >>= 1) {
        if (tid < s) sv[tid] = fmaxf(sv[tid], sv[tid + s]);
        __syncthreads();
    }
    float mx = sv[0];
    __syncthreads();
    float e = (tid < Cc) ? expf(v - mx) : 0.f;
    sv[tid] = e;
    __syncthreads();
    for (int s = 64; s > 0; s >>= 1) {
        if (tid < s) sv[tid] += sv[tid + s];
        __syncthreads();
    }
    float inv = 1.0f / sv[0];
    if (tid < Cc) g_attn[b * Cc + tid] = e * inv;
}

// fused: ctx (attn-weighted sum over c) AND mean (uniform sum over c) in ONE 52MB scan
__global__ void k_meanctx(const float* __restrict__ enc) {
    __shared__ float at[Cc];
    int idx = blockIdx.x * 256 + threadIdx.x;       // 131072 threads, 8 blocks per b
    int b = idx >> 11, f = idx & 2047;
    if (threadIdx.x < Cc) at[threadIdx.x] = g_attn[b * Cc + threadIdx.x];
    __syncthreads();
    const float* p = enc + (size_t)b * Cc * Ff + f;
    float sc = 0.f, sm = 0.f;
#pragma unroll 8
    for (int c = 0; c < Cc; c++) {
        float v = p[c * Ff];
        sc = fmaf(at[c], v, sc);
        sm += v;
    }
    g_ctxT[f * B + b] = sc;
    g_meanT[f * B + b] = sm * (1.0f / Cc);
}

// h0/c0 partials: grid (30, 4). bx -> 20-col group (600 cols: 0..299 Wh0, 300..599 Wc0,
// boundary at group 15), by -> 512-k chunk. Thread: 4 cols, 1 x-LDS + LDS.128 w per 4 MACs.
__global__ void k_h0c0p(const float* __restrict__ Wh0, const float* __restrict__ Wc0) {
    __shared__ float4 xs4[128 * 16];    // 32 KB
    __shared__ float4 ws4[128 * 5];     // 10 KB  [kk][20 cols]
    int tid = threadIdx.x;
    int b = tid & 63, jq = tid >> 6;
    int colbase = blockIdx.x * 20;
    const float* W = (blockIdx.x >= 15) ? Wc0 : Wh0;
    int cb = (blockIdx.x >= 15) ? colbase - 300 : colbase;
    int kbase = blockIdx.y * 512;
    float* wsf = (float*)ws4;
    ull aA = pk2(0.f, 0.f), aB = pk2(0.f, 0.f);
    for (int sub = 0; sub < 4; sub++) {
        int k0 = kbase + sub * 128;
        __syncthreads();
        const float4* xsrc = (const float4*)g_meanT + k0 * 16;
        for (int i = tid; i < 2048; i += 320) xs4[i] = xsrc[i];
        for (int i = tid; i < 2560; i += 320) {
            int kk = i / 20, c = i - kk * 20;
            wsf[i] = W[(size_t)(k0 + kk) * H + cb + c];
        }
        __syncthreads();
        const float* xc = ((const float*)xs4) + b;
        const ulonglong2* wp = ((const ulonglong2*)ws4) + jq;
#pragma unroll 16
        for (int kk = 0; kk < 128; kk++) {
            float x = xc[kk * 64];
            ull xx = pk2(x, x);
            ulonglong2 w = wp[kk * 5];
            fma2(aA, xx, w.x);
            fma2(aB, xx, w.y);
        }
    }
    float2 rA = upk2(aA), rB = upk2(aB);
    float* dst = g_p0 + blockIdx.y * (600 * B) + (colbase + jq * 4) * B + b;
    dst[0] = rA.x; dst[B] = rA.y; dst[2 * B] = rB.x; dst[3 * B] = rB.y;
}

// reduce h0c0 partials: tanh(sum + bias) -> g_hB[0] (b-major) / g_cT
__global__ void k_h0red(const float* __restrict__ bh0, const float* __restrict__ bc0) {
    int idx = blockIdx.x * 256 + threadIdx.x;       // 38400
    int col = idx >> 6, b = idx & 63;
    float s = g_p0[idx] + g_p0[600 * B + idx] + g_p0[2 * 600 * B + idx] + g_p0[3 * 600 * B + idx];
    if (col < 300) {
        g_hB[b * HB_PITCH + col] = tanhf(s + bh0[col]);
    } else {
        g_cT[(col - 300) * B + b] = tanhf(s + bc0[col - 300]);
    }
}

// CWT partials: grid (75, 2). bx -> 20-col group of j (gate boundaries mult of 20),
// by -> 1024-k half. Same inner structure as k_h0c0p.
__global__ void k_cwp(const float* __restrict__ Wi, const float* __restrict__ Wf,
                      const float* __restrict__ Wo, const float* __restrict__ Wg,
                      const float* __restrict__ Wcp) {
    __shared__ float4 xs4[128 * 16];    // 32 KB
    __shared__ float4 ws4[128 * 5];     // 10 KB
    int tid = threadIdx.x;
    int b = tid & 63, jq = tid >> 6;
    int j0 = blockIdx.x * 20;
    const float* wbase;
    if (j0 < 1200) {
        int gate = j0 / 300, col = j0 - gate * 300;
        const float* Wx = (gate == 0) ? Wi : (gate == 1) ? Wf : (gate == 2) ? Wo : Wg;
        wbase = Wx + 600 * H + col;     // ctx rows start at comb row 600
    } else {
        wbase = Wcp + (j0 - 1200);
    }
    int kbase = blockIdx.y * 1024;
    float* wsf = (float*)ws4;
    ull aA = pk2(0.f, 0.f), aB = pk2(0.f, 0.f);
    for (int sub = 0; sub < 8; sub++) {
        int k0 = kbase + sub * 128;
        __syncthreads();
        const float4* xsrc = (const float4*)g_ctxT + k0 * 16;
        for (int i = tid; i < 2048; i += 320) xs4[i] = xsrc[i];
        for (int i = tid; i < 2560; i += 320) {
            int kk = i / 20, c = i - kk * 20;
            wsf[i] = wbase[(size_t)(k0 + kk) * H + c];
        }
        __syncthreads();
        const float* xc = ((const float*)xs4) + b;
        const ulonglong2* wp = ((const ulonglong2*)ws4) + jq;
#pragma unroll 16
        for (int kk = 0; kk < 128; kk++) {
            float x = xc[kk * 64];
            ull xx = pk2(x, x);
            ulonglong2 w = wp[kk * 5];
            fma2(aA, xx, w.x);
            fma2(aB, xx, w.y);
        }
    }
    float2 rA = upk2(aA), rB = upk2(aB);
    float* dst = g_pcw + blockIdx.y * (1500 * B) + (j0 + jq * 4) * B + b;
    dst[0] = rA.x; dst[B] = rA.y; dst[2 * B] = rB.x; dst[3 * B] = rB.y;
}

__global__ void k_cwred() {
    int idx = blockIdx.x * 256 + threadIdx.x;       // 96000
    g_CWT[idx] = g_pcw[idx] + g_pcw[1500 * B + idx];
}

// baseT[t][j][b] = bias_g[col] + CWT[j][b] + emb[cap[b][t]] @ (gate emb-rows)
__global__ void k_base(const int* __restrict__ caps, const float* __restrict__ emb,
                       const float* __restrict__ Wi, const float* __restrict__ Wf,
                       const float* __restrict__ Wo, const float* __restrict__ Wg,
                       const float* __restrict__ bi, const float* __restrict__ bf,
                       const float* __restrict__ bo, const float* __restrict__ bg) {
    __shared__ float xs[64 * 61];
    __shared__ float ws[300 * 20];      // 24 KB
    __shared__ int cap_s[64];
    int tid = threadIdx.x;              // 320
    int t = blockIdx.y;
    int b = tid & 63, jq = tid >> 6;
    int jB = blockIdx.x * 20;           // block col base; gate boundaries mult of 20
    int gate = jB / 300, colB = jB - gate * 300;
    int j0 = jB + jq * 4;
    int col0 = colB + jq * 4;
    const float* Wx = (gate == 0) ? Wi : (gate == 1) ? Wf : (gate == 2) ? Wo : Wg;
    const float* bx = (gate == 0) ? bi : (gate == 1) ? bf : (gate == 2) ? bo : bg;
    if (tid < 64) cap_s[tid] = caps[tid * T + t];
    for (int i = tid; i < 300 * 20; i += 320) {
        int kk = i / 20, c = i - kk * 20;
        ws[i] = Wx[(size_t)kk * H + colB + c];
    }
    __syncthreads();
    ull a01 = pk2(bx[col0 + 0] + g_CWT[(j0 + 0) * B + b],
                  bx[col0 + 1] + g_CWT[(j0 + 1) * B + b]);
    ull a23 = pk2(bx[col0 + 2] + g_CWT[(j0 + 2) * B + b],
                  bx[col0 + 3] + g_CWT[(j0 + 3) * B + b]);
    for (int c0 = 0; c0 < H; c0 += 60) {
        __syncthreads();
        for (int i = tid; i < 64 * 60; i += 320) {
            int bb = i / 60, kk = i - bb * 60;
            xs[bb * 61 + kk] = emb[(size_t)cap_s[bb] * H + c0 + kk];
        }
        __syncthreads();
        const float* wp = ws + c0 * 20 + jq * 4;
#pragma unroll 10
        for (int kk = 0; kk < 60; kk++) {
            float x = xs[b * 61 + kk];
            ull xx = pk2(x, x);
            ulonglong2 w = *(const ulonglong2*)(wp + kk * 20);
            fma2(a01, xx, w.x);
            fma2(a23, xx, w.y);
        }
    }
    float2 r01 = upk2(a01), r23 = upk2(a23);
    int base = t * 1200;
    g_baseT[(base + j0 + 0) * B + b] = r01.x;
    g_baseT[(base + j0 + 1) * B + b] = r01.y;
    g_baseT[(base + j0 + 2) * B + b] = r23.x;
    g_baseT[(base + j0 + 3) * B + b] = r23.y;
}

// sbT[t][k][b] = emb_t[b][k] + ctx@Wcp[k] + bcp[k] + bhp[k]
__global__ void k_sb(const int* __restrict__ caps, const float* __restrict__ emb,
                     const float* __restrict__ bcp, const float* __restrict__ bhp) {
    int idx = blockIdx.x * 256 + threadIdx.x;
    if (idx >= 31 * H * B) return;
    int b = idx & 63, r = idx >> 6;
    int k = r % H, t = r / H;
    int cap = caps[b * T + t];
    g_sbT[idx] = emb[(size_t)cap * H + k] + g_CWT[(1200 + k) * B + b] + bcp[k] + bhp[k];
}

// pbT[t][jj][b] = bop[jj] + sum_k sbT[t][k][b] * Wop[k][jj]; w tile staged in smem
__global__ void k_pbase(const float* __restrict__ Wop, const float* __restrict__ bop) {
    __shared__ float ws[300 * 20];      // 24 KB
    int tid = threadIdx.x;              // 320
    int t = blockIdx.y;
    int b = tid & 63, jq = tid >> 6;
    int jB = blockIdx.x * 20;
    int j0 = jB + jq * 4;               // grid.x=15 -> j0 < 300
    for (int i = tid; i < 300 * 20; i += 320) {
        int kk = i / 20, c = i - kk * 20;
        ws[i] = Wop[(size_t)kk * H + jB + c];
    }
    __syncthreads();
    ull a01 = pk2(bop[j0], bop[j0 + 1]);
    ull a23 = pk2(bop[j0 + 2], bop[j0 + 3]);
    const float* xp = g_sbT + t * H * B + b;
    const float* wp = ws + jq * 4;
#pragma unroll 10
    for (int k = 0; k < H; k++) {
        float x = xp[k * B];
        ull xx = pk2(x, x);
        ulonglong2 w = *(const ulonglong2*)(wp + k * 20);
        fma2(a01, xx, w.x);
        fma2(a23, xx, w.y);
    }
    float2 r01 = upk2(a01), r23 = upk2(a23);
    int base = t * H;
    g_pbT[(base + j0 + 0) * B + b] = r01.x;
    g_pbT[(base + j0 + 1) * B + b] = r01.y;
    g_pbT[(base + j0 + 2) * B + b] = r23.x;
    g_pbT[(base + j0 + 3) * B + b] = r23.y;
}

// WW = Whp @ Wop  (300x300); also resets the grid-sync counter for this launch
__global__ void k_ww(const float* __restrict__ Whp, const float* __restrict__ Wop) {
    int idx = blockIdx.x * 256 + threadIdx.x;
    if (idx == 0) g_cnt = 0;
    if (idx >= H * H) return;
    int k = idx / H, jj = idx - k * H;
    float s = 0.f;
    const float* a = Whp + k * H;
    const float* w = Wop + jj;
#pragma unroll 4
    for (int m = 0; m < H; m++) s += a[m] * w[m * H];
    g_WW[idx] = s;
}

__global__ void k_out0(const float* __restrict__ emb, float* __restrict__ out) {
    int idx = blockIdx.x * 256 + threadIdx.x;
    if (idx >= B * H) return;
    int b = idx / H, jj = idx - b * H;
    out[(size_t)b * T * H + jj] = emb[1 * H + jj];   // BOS = 1
}

// ------------------- persistent recurrence kernel (ONE launch, 32 steps) -------------------
// 148 blocks x 320 threads. Blocks 0..3 own 3 hh cols, 4..147 own 2. Weights [m][c][k]
// in smem once. Per step: whole h[t] (64x300, b-major) staged via float4 into dynamic smem,
// then dot is pure LDS.128 pairs (x ull2 + w ull2 + 2 FFMA2 per 4k per col).
__global__ void __launch_bounds__(320, 1) k_steps(
        const float* __restrict__ Wi, const float* __restrict__ Wf,
        const float* __restrict__ Wo, const float* __restrict__ Wg,
        float* __restrict__ out) {
    extern __shared__ float smem[];
    float* xs = smem;                   // [b][300]  (pitch 300: 12-bank stride, conflict-free)
    float* sw = smem + 64 * 300;        // [m][c][300], 5*3*300
    float* ex = sw + 4500;              // gate exchange [gate][c*64+b]
    float* cs = ex + 768;               // cell state [c*64+b]

    int tid = threadIdx.x;
    int b = tid & 63, m = tid >> 6;          // m in [0,5)
    int bid = blockIdx.x;
    int nc  = (bid < 4) ? 3 : 2;
    int hh0 = (bid < 4) ? bid * 3 : 12 + (bid - 4) * 2;

    // ---- stage this block's weight slice into smem (once) ----
    for (int i = tid; i < 5 * 3 * 300; i += 320) {
        int k = i % 300, rc = i / 300;
        int mm = rc / 3, c = rc - mm * 3;
        if (c < nc) {
            float v;
            if (mm < 4) {
                const float* Wx = (mm == 0) ? Wi : (mm == 1) ? Wf : (mm == 2) ? Wo : Wg;
                v = Wx[(size_t)(300 + k) * H + hh0 + c];   // h rows of comb start at 300
            } else {
                v = g_WW[k * H + hh0 + c];
            }
            sw[i] = v;
        }
    }
    if (tid < nc * 64) {
        cs[tid] = g_cT[(hh0 + (tid >> 6)) * B + (tid & 63)];
    }
    __syncthreads();

    for (int t = 0; t < T; t++) {
        // ---- stage h[t] ([b][k] global, pitch 304) into xs ----
        const float4* hsrc = (const float4*)(g_hB + (size_t)t * 64 * HB_PITCH);
#pragma unroll
        for (int i = tid; i < 4800; i += 320) {
            int bb = i / 75, g = i - bb * 75;
            ((float4*)(xs + bb * 300))[g] = hsrc[bb * (HB_PITCH / 4) + g];
        }
        __syncthreads();

        bool gatew = (m < 4);
        bool act = gatew ? (t < 31) : (t > 0);
        float b0 = 0.f, b1 = 0.f, b2 = 0.f;
        if (act) {
            if (gatew) {
                int base = (t * 1200 + m * 300 + hh0) * B + b;
                b0 = g_baseT[base]; b1 = g_baseT[base + B];
                if (nc == 3) b2 = g_baseT[base + 2 * B];
            } else {
                int base = ((t - 1) * H + hh0) * B + b;
                b0 = g_pbT[base]; b1 = g_pbT[base + B];
                if (nc == 3) b2 = g_pbT[base + 2 * B];
            }
        }
        ull ac0 = pk2(b0, 0.f), ac1 = pk2(b1, 0.f), ac2 = pk2(b2, 0.f);
        if (act) {
            const ulonglong2* xp = (const ulonglong2*)(xs + b * 300);
            const ulonglong2* w0 = (const ulonglong2*)(sw + (m * 3 + 0) * 300);
            const ulonglong2* w1 = (const ulonglong2*)(sw + (m * 3 + 1) * 300);
            if (nc == 2) {
#pragma unroll 15
                for (int g = 0; g < 75; g++) {
                    ulonglong2 xv = xp[g];
                    ulonglong2 wa = w0[g];
                    fma2(ac0, xv.x, wa.x); fma2(ac0, xv.y, wa.y);
                    ulonglong2 wb = w1[g];
                    fma2(ac1, xv.x, wb.x); fma2(ac1, xv.y, wb.y);
                }
            } else {
                const ulonglong2* w2 = (const ulonglong2*)(sw + (m * 3 + 2) * 300);
#pragma unroll 15
                for (int g = 0; g < 75; g++) {
                    ulonglong2 xv = xp[g];
                    ulonglong2 wa = w0[g];
                    fma2(ac0, xv.x, wa.x); fma2(ac0, xv.y, wa.y);
                    ulonglong2 wb = w1[g];
                    fma2(ac1, xv.x, wb.x); fma2(ac1, xv.y, wb.y);
                    ulonglong2 wc = w2[g];
                    fma2(ac2, xv.x, wc.x); fma2(ac2, xv.y, wc.y);
                }
            }
        }
        float2 f0 = upk2(ac0), f1 = upk2(ac1), f2 = upk2(ac2);
        float r0 = f0.x + f0.y, r1 = f1.x + f1.y, r2 = f2.x + f2.y;

        // ---- pred output (m==4) ----
        if (!gatew && t > 0) {
            size_t o = ((size_t)b * T + t) * H + hh0;
            out[o] = r0; out[o + 1] = r1;
            if (nc == 3) out[o + 2] = r2;
        }

        if (t < 31) {
            // ---- exchange gate pre-acts, pointwise LSTM update ----
            if (gatew) {
                ex[m * 192 + b]       = r0;
                ex[m * 192 + 64 + b]  = r1;
                if (nc == 3) ex[m * 192 + 128 + b] = r2;
            }
            __syncthreads();
            if (tid < nc * 64) {
                int c = tid >> 6, bb = tid & 63;
                float ai = ex[tid];
                float af = ex[192 + tid];
                float ao = ex[384 + tid];
                float ag = ex[576 + tid];
                float iv = 1.f / (1.f + expf(-ai));
                float fv = 1.f / (1.f + expf(-af));
                float ov = 1.f / (1.f + expf(-ao));
                float gv = tanhf(ag);
                float cn = fv * cs[tid] + iv * gv;
                cs[tid] = cn;
                g_hB[(size_t)(t + 1) * 64 * HB_PITCH + bb * HB_PITCH + hh0 + c] = ov * tanhf(cn);
            }
            // ---- grid barrier: all h writes visible before next step's reads ----
            __threadfence();
            __syncthreads();
            if (tid == 0) {
                atomicAdd(&g_cnt, 1u);
                unsigned target = (unsigned)NBLK * (unsigned)(t + 1);
                while (*((volatile unsigned*)&g_cnt) < target) { }
            }
            __syncthreads();
        }
    }
}

// ------------------- launch -------------------
extern "C" void kernel_launch(void* const* d_in, const int* in_sizes, int n_in,
                              void* d_out, int out_size) {
    const float* enc    = (const float*)d_in[0];
    const int*   caps   = (const int*)d_in[1];
    const float* emb    = (const float*)d_in[2];
    const float* Wh0    = (const float*)d_in[3];
    const float* bh0    = (const float*)d_in[4];
    const float* Wc0    = (const float*)d_in[5];
    const float* bc0    = (const float*)d_in[6];
    const float* We_enc = (const float*)d_in[7];
    // d_in[8] We_hid, d_in[9] be: unused — constant shifts inside softmax cancel.
    const float* Wi  = (const float*)d_in[10];
    const float* bi  = (const float*)d_in[11];
    const float* Wf  = (const float*)d_in[12];
    const float* bf  = (const float*)d_in[13];
    const float* Wo  = (const float*)d_in[14];
    const float* bo  = (const float*)d_in[15];
    const float* Wg  = (const float*)d_in[16];
    const float* bg  = (const float*)d_in[17];
    const float* Wcp = (const float*)d_in[18];
    const float* bcp = (const float*)d_in[19];
    const float* Whp = (const float*)d_in[20];
    const float* bhp = (const float*)d_in[21];
    const float* Wop = (const float*)d_in[22];
    const float* bop = (const float*)d_in[23];
    float* out = (float*)d_out;

    cudaFuncSetAttribute(k_steps, cudaFuncAttributeMaxDynamicSharedMemorySize, STEP_SMEM);

    k_eenc<<<1600, 128>>>(enc, We_enc);
    k_softmax<<<64, 128>>>();
    k_meanctx<<<512, 256>>>(enc);
    {
        dim3 gh(30, 4);
        k_h0c0p<<<gh, 320>>>(Wh0, Wc0);
    }
    k_h0red<<<150, 256>>>(bh0, bc0);
    {
        dim3 gc(75, 2);
        k_cwp<<<gc, 320>>>(Wi, Wf, Wo, Wg, Wcp);
    }
    k_cwred<<<375, 256>>>();
    {
        dim3 gb(60, 31);
        k_base<<<gb, 320>>>(caps, emb, Wi, Wf, Wo, Wg, bi, bf, bo, bg);
    }
    k_sb<<<(31 * H * B + 255) / 256, 256>>>(caps, emb, bcp, bhp);
    {
        dim3 gp(15, 31);
        k_pbase<<<gp, 320>>>(Wop, bop);
    }
    k_ww<<<(H * H + 255) / 256, 256>>>(Whp, Wop);
    k_out0<<<(B * H + 255) / 256, 256>>>(emb, out);

    k_steps<<<NBLK, 320, STEP_SMEM>>>(Wi, Wf, Wo, Wg, out);
}

// round 7
// speedup vs baseline: 7.5133x; 1.0248x over previous
#include <cuda_runtime.h>
#include <math.h>

#define B 64
#define Cc 100
#define Ff 2048
#define T 32
#define H 300
#define NBLK 148   // persistent step-kernel grid == SM count
#define HB_PITCH 304          // g_hB row pitch (floats), 16B-aligned rows
#define STEP_SMEM 98640       // k_steps dynamic smem bytes

typedef unsigned long long ull;

// packed f32x2 helpers (numerics identical to 2x fmaf)
__device__ __forceinline__ ull pk2(float x, float y) {
    ull r; asm("mov.b64 %0, {%1,%2};" : "=l"(r) : "f"(x), "f"(y)); return r;
}
__device__ __forceinline__ void fma2(ull& d, ull a, ull b) {
    asm("fma.rn.f32x2 %0, %1, %2, %3;" : "=l"(d) : "l"(a), "l"(b), "l"(d));
}
__device__ __forceinline__ float2 upk2(ull v) {
    float2 r; asm("mov.b64 {%0,%1}, %2;" : "=f"(r.x), "=f"(r.y) : "l"(v)); return r;
}

// ------------------- scratch (static device memory, no allocs) -------------------
__device__ float g_meanT[Ff * B];         // mean over C, transposed [f][b]
__device__ float g_eenc[B * Cc];          // enc @ We_enc
__device__ float g_attn[B * Cc];          // softmax(e_enc)  (time-invariant!)
__device__ float g_ctxT[Ff * B];          // ctx transposed [f][b]
__device__ float g_cT[H * B];             // cell state init [hh][b]
__device__ float g_hB[T * 64 * HB_PITCH]; // hidden state [t][b][k], fresh rows per step
__device__ float g_CWT[1504 * B];         // ctx @ [Wi|Wf|Wo|Wg ctx-rows, Wcp], [j][b]
__device__ float g_baseT[31 * 1200 * B];  // per-step gate pre-act base [t][j][b]
__device__ float g_sbT[31 * H * B];       // sbase [t][k][b]
__device__ float g_pbT[31 * H * B];       // pbase = sbase@Wop + bop, [t][jj][b]
__device__ float g_WW[H * H];             // Whp @ Wop
__device__ float g_p0[8 * 600 * B];       // h0c0 k-split partials
__device__ float g_pcw[4 * 1500 * B];     // cw k-split partials
__device__ volatile unsigned g_arr[NBLK * 32]; // per-block arrival flags, 128B stride
__device__ volatile unsigned g_go;             // broadcast go word

// ------------------- prologue kernels -------------------

// one warp per (b,c) row: coalesced 512B/warp-load + shuffle reduce
__global__ void k_eenc(const float* __restrict__ enc, const float* __restrict__ We) {
    int w = blockIdx.x * 4 + (threadIdx.x >> 5);    // 1600 blocks x 128
    int lane = threadIdx.x & 31;
    if (w >= B * Cc) return;
    const float4* row = (const float4*)(enc + (size_t)w * Ff);
    const float4* wv = (const float4*)We;
    float s = 0.f;
#pragma unroll
    for (int i = 0; i < Ff / 4; i += 32) {
        float4 a = row[i + lane], c4 = wv[i + lane];
        s += a.x * c4.x + a.y * c4.y + a.z * c4.z + a.w * c4.w;
    }
#pragma unroll
    for (int o = 16; o > 0; o >>= 1) s += __shfl_down_sync(0xffffffffu, s, o);
    if (lane == 0) g_eenc[w] = s;
}

// softmax over C=100 per batch row. (h-dot and be are constant shifts -> dropped)
__global__ void k_softmax() {
    __shared__ float sv[128];
    int b = blockIdx.x, tid = threadIdx.x;
    float v = (tid < Cc) ? g_eenc[b * Cc + tid] : -1e30f;
    sv[tid] = v;
    __syncthreads();
    for (int s = 64; s > 0; s >>= 1) {
        if (tid < s) sv[tid] = fmaxf(sv[tid], sv[tid + s]);
        __syncthreads();
    }
    float mx = sv[0];
    __syncthreads();
    float e = (tid < Cc) ? expf(v - mx) : 0.f;
    sv[tid] = e;
    __syncthreads();
    for (int s = 64; s > 0; s >>= 1) {
        if (tid < s) sv[tid] += sv[tid + s];
        __syncthreads();
    }
    float inv = 1.0f / sv[0];
    if (tid < Cc) g_attn[b * Cc + tid] = e * inv;
}

// fused ctx+mean scan, float4 per thread: 256 blocks x 128 thr, 4 f per thread
__global__ void k_meanctx(const float* __restrict__ enc) {
    __shared__ float at[Cc];
    int b = blockIdx.x >> 2;
    int f4 = (blockIdx.x & 3) * 128 + threadIdx.x;  // 0..511
    if (threadIdx.x < Cc) at[threadIdx.x] = g_attn[b * Cc + threadIdx.x];
    __syncthreads();
    const float4* p = (const float4*)(enc + (size_t)b * Cc * Ff) + f4;
    float4 sc = make_float4(0.f, 0.f, 0.f, 0.f);
    float4 sm = make_float4(0.f, 0.f, 0.f, 0.f);
#pragma unroll 10
    for (int c = 0; c < Cc; c++) {
        float4 v = p[c * (Ff / 4)];
        float a = at[c];
        sc.x = fmaf(a, v.x, sc.x); sc.y = fmaf(a, v.y, sc.y);
        sc.z = fmaf(a, v.z, sc.z); sc.w = fmaf(a, v.w, sc.w);
        sm.x += v.x; sm.y += v.y; sm.z += v.z; sm.w += v.w;
    }
    int f = f4 * 4;
    g_ctxT[(f + 0) * B + b] = sc.x; g_ctxT[(f + 1) * B + b] = sc.y;
    g_ctxT[(f + 2) * B + b] = sc.z; g_ctxT[(f + 3) * B + b] = sc.w;
    const float r = 1.0f / Cc;
    g_meanT[(f + 0) * B + b] = sm.x * r; g_meanT[(f + 1) * B + b] = sm.y * r;
    g_meanT[(f + 2) * B + b] = sm.z * r; g_meanT[(f + 3) * B + b] = sm.w * r;
}

// h0/c0 partials: grid (30, 8). bx -> 20-col group (600 cols: 0..299 Wh0, 300..599 Wc0),
// by -> 256-k chunk. Thread: 4 cols, 1 x-LDS + LDS.128 w per 4 MACs.
__global__ void __launch_bounds__(320, 1) k_h0c0p(
        const float* __restrict__ Wh0, const float* __restrict__ Wc0) {
    __shared__ float4 xs4[128 * 16];    // 32 KB
    __shared__ float4 ws4[128 * 5];     // 10 KB  [kk][20 cols]
    int tid = threadIdx.x;
    int b = tid & 63, jq = tid >> 6;
    int colbase = blockIdx.x * 20;
    const float* W = (blockIdx.x >= 15) ? Wc0 : Wh0;
    int cb = (blockIdx.x >= 15) ? colbase - 300 : colbase;
    int kbase = blockIdx.y * 256;
    float* wsf = (float*)ws4;
    ull aA = pk2(0.f, 0.f), aB = pk2(0.f, 0.f);
    for (int sub = 0; sub < 2; sub++) {
        int k0 = kbase + sub * 128;
        __syncthreads();
        const float4* xsrc = (const float4*)g_meanT + k0 * 16;
        for (int i = tid; i < 2048; i += 320) xs4[i] = xsrc[i];
        for (int i = tid; i < 2560; i += 320) {
            int kk = i / 20, c = i - kk * 20;
            wsf[i] = W[(size_t)(k0 + kk) * H + cb + c];
        }
        __syncthreads();
        const float* xc = ((const float*)xs4) + b;
        const ulonglong2* wp = ((const ulonglong2*)ws4) + jq;
#pragma unroll 16
        for (int kk = 0; kk < 128; kk++) {
            float x = xc[kk * 64];
            ull xx = pk2(x, x);
            ulonglong2 w = wp[kk * 5];
            fma2(aA, xx, w.x);
            fma2(aB, xx, w.y);
        }
    }
    float2 rA = upk2(aA), rB = upk2(aB);
    float* dst = g_p0 + blockIdx.y * (600 * B) + (colbase + jq * 4) * B + b;
    dst[0] = rA.x; dst[B] = rA.y; dst[2 * B] = rB.x; dst[3 * B] = rB.y;
}

// reduce h0c0 partials: tanh(sum + bias) -> g_hB[0] (b-major) / g_cT
__global__ void k_h0red(const float* __restrict__ bh0, const float* __restrict__ bc0) {
    int idx = blockIdx.x * 256 + threadIdx.x;       // 38400
    int col = idx >> 6, b = idx & 63;
    float s = 0.f;
#pragma unroll
    for (int j = 0; j < 8; j++) s += g_p0[j * 600 * B + idx];
    if (col < 300) {
        g_hB[b * HB_PITCH + col] = tanhf(s + bh0[col]);
    } else {
        g_cT[(col - 300) * B + b] = tanhf(s + bc0[col - 300]);
    }
}

// CWT partials: grid (75, 4). bx -> 20-col group of j (gate boundaries mult of 20),
// by -> 512-k chunk. Same inner structure as k_h0c0p.
__global__ void __launch_bounds__(320, 1) k_cwp(
        const float* __restrict__ Wi, const float* __restrict__ Wf,
        const float* __restrict__ Wo, const float* __restrict__ Wg,
        const float* __restrict__ Wcp) {
    __shared__ float4 xs4[128 * 16];    // 32 KB
    __shared__ float4 ws4[128 * 5];     // 10 KB
    int tid = threadIdx.x;
    int b = tid & 63, jq = tid >> 6;
    int j0 = blockIdx.x * 20;
    const float* wbase;
    if (j0 < 1200) {
        int gate = j0 / 300, col = j0 - gate * 300;
        const float* Wx = (gate == 0) ? Wi : (gate == 1) ? Wf : (gate == 2) ? Wo : Wg;
        wbase = Wx + 600 * H + col;     // ctx rows start at comb row 600
    } else {
        wbase = Wcp + (j0 - 1200);
    }
    int kbase = blockIdx.y * 512;
    float* wsf = (float*)ws4;
    ull aA = pk2(0.f, 0.f), aB = pk2(0.f, 0.f);
    for (int sub = 0; sub < 4; sub++) {
        int k0 = kbase + sub * 128;
        __syncthreads();
        const float4* xsrc = (const float4*)g_ctxT + k0 * 16;
        for (int i = tid; i < 2048; i += 320) xs4[i] = xsrc[i];
        for (int i = tid; i < 2560; i += 320) {
            int kk = i / 20, c = i - kk * 20;
            wsf[i] = wbase[(size_t)(k0 + kk) * H + c];
        }
        __syncthreads();
        const float* xc = ((const float*)xs4) + b;
        const ulonglong2* wp = ((const ulonglong2*)ws4) + jq;
#pragma unroll 16
        for (int kk = 0; kk < 128; kk++) {
            float x = xc[kk * 64];
            ull xx = pk2(x, x);
            ulonglong2 w = wp[kk * 5];
            fma2(aA, xx, w.x);
            fma2(aB, xx, w.y);
        }
    }
    float2 rA = upk2(aA), rB = upk2(aB);
    float* dst = g_pcw + blockIdx.y * (1500 * B) + (j0 + jq * 4) * B + b;
    dst[0] = rA.x; dst[B] = rA.y; dst[2 * B] = rB.x; dst[3 * B] = rB.y;
}

__global__ void k_cwred() {
    int idx = blockIdx.x * 256 + threadIdx.x;       // 96000
    g_CWT[idx] = g_pcw[idx] + g_pcw[1500 * B + idx]
               + g_pcw[2 * 1500 * B + idx] + g_pcw[3 * 1500 * B + idx];
}

// baseT[t][j][b] = bias_g[col] + CWT[j][b] + emb[cap[b][t]] @ (gate emb-rows)
__global__ void k_base(const int* __restrict__ caps, const float* __restrict__ emb,
                       const float* __restrict__ Wi, const float* __restrict__ Wf,
                       const float* __restrict__ Wo, const float* __restrict__ Wg,
                       const float* __restrict__ bi, const float* __restrict__ bf,
                       const float* __restrict__ bo, const float* __restrict__ bg) {
    __shared__ float xs[64 * 61];
    __shared__ float ws[300 * 20];      // 24 KB
    __shared__ int cap_s[64];
    int tid = threadIdx.x;              // 320
    int t = blockIdx.y;
    int b = tid & 63, jq = tid >> 6;
    int jB = blockIdx.x * 20;           // block col base; gate boundaries mult of 20
    int gate = jB / 300, colB = jB - gate * 300;
    int j0 = jB + jq * 4;
    int col0 = colB + jq * 4;
    const float* Wx = (gate == 0) ? Wi : (gate == 1) ? Wf : (gate == 2) ? Wo : Wg;
    const float* bx = (gate == 0) ? bi : (gate == 1) ? bf : (gate == 2) ? bo : bg;
    if (tid < 64) cap_s[tid] = caps[tid * T + t];
    for (int i = tid; i < 300 * 20; i += 320) {
        int kk = i / 20, c = i - kk * 20;
        ws[i] = Wx[(size_t)kk * H + colB + c];
    }
    __syncthreads();
    ull a01 = pk2(bx[col0 + 0] + g_CWT[(j0 + 0) * B + b],
                  bx[col0 + 1] + g_CWT[(j0 + 1) * B + b]);
    ull a23 = pk2(bx[col0 + 2] + g_CWT[(j0 + 2) * B + b],
                  bx[col0 + 3] + g_CWT[(j0 + 3) * B + b]);
    for (int c0 = 0; c0 < H; c0 += 60) {
        __syncthreads();
        for (int i = tid; i < 64 * 60; i += 320) {
            int bb = i / 60, kk = i - bb * 60;
            xs[bb * 61 + kk] = emb[(size_t)cap_s[bb] * H + c0 + kk];
        }
        __syncthreads();
        const float* wp = ws + c0 * 20 + jq * 4;
#pragma unroll 10
        for (int kk = 0; kk < 60; kk++) {
            float x = xs[b * 61 + kk];
            ull xx = pk2(x, x);
            ulonglong2 w = *(const ulonglong2*)(wp + kk * 20);
            fma2(a01, xx, w.x);
            fma2(a23, xx, w.y);
        }
    }
    float2 r01 = upk2(a01), r23 = upk2(a23);
    int base = t * 1200;
    g_baseT[(base + j0 + 0) * B + b] = r01.x;
    g_baseT[(base + j0 + 1) * B + b] = r01.y;
    g_baseT[(base + j0 + 2) * B + b] = r23.x;
    g_baseT[(base + j0 + 3) * B + b] = r23.y;
}

// sbT[t][k][b] = emb_t[b][k] + ctx@Wcp[k] + bcp[k] + bhp[k]
__global__ void k_sb(const int* __restrict__ caps, const float* __restrict__ emb,
                     const float* __restrict__ bcp, const float* __restrict__ bhp) {
    int idx = blockIdx.x * 256 + threadIdx.x;
    if (idx >= 31 * H * B) return;
    int b = idx & 63, r = idx >> 6;
    int k = r % H, t = r / H;
    int cap = caps[b * T + t];
    g_sbT[idx] = emb[(size_t)cap * H + k] + g_CWT[(1200 + k) * B + b] + bcp[k] + bhp[k];
}

// pbT[t][jj][b] = bop[jj] + sum_k sbT[t][k][b] * Wop[k][jj]; w tile staged in smem
__global__ void k_pbase(const float* __restrict__ Wop, const float* __restrict__ bop) {
    __shared__ float ws[300 * 20];      // 24 KB
    int tid = threadIdx.x;              // 320
    int t = blockIdx.y;
    int b = tid & 63, jq = tid >> 6;
    int jB = blockIdx.x * 20;
    int j0 = jB + jq * 4;               // grid.x=15 -> j0 < 300
    for (int i = tid; i < 300 * 20; i += 320) {
        int kk = i / 20, c = i - kk * 20;
        ws[i] = Wop[(size_t)kk * H + jB + c];
    }
    __syncthreads();
    ull a01 = pk2(bop[j0], bop[j0 + 1]);
    ull a23 = pk2(bop[j0 + 2], bop[j0 + 3]);
    const float* xp = g_sbT + t * H * B + b;
    const float* wp = ws + jq * 4;
#pragma unroll 10
    for (int k = 0; k < H; k++) {
        float x = xp[k * B];
        ull xx = pk2(x, x);
        ulonglong2 w = *(const ulonglong2*)(wp + k * 20);
        fma2(a01, xx, w.x);
        fma2(a23, xx, w.y);
    }
    float2 r01 = upk2(a01), r23 = upk2(a23);
    int base = t * H;
    g_pbT[(base + j0 + 0) * B + b] = r01.x;
    g_pbT[(base + j0 + 1) * B + b] = r01.y;
    g_pbT[(base + j0 + 2) * B + b] = r23.x;
    g_pbT[(base + j0 + 3) * B + b] = r23.y;
}

// WW = Whp @ Wop  (300x300); also resets the barrier flags for this launch
__global__ void k_ww(const float* __restrict__ Whp, const float* __restrict__ Wop) {
    int idx = blockIdx.x * 256 + threadIdx.x;
    if (idx < NBLK) g_arr[idx * 32] = 0;
    if (idx == 0) g_go = 0;
    if (idx >= H * H) return;
    int k = idx / H, jj = idx - k * H;
    float s = 0.f;
    const float* a = Whp + k * H;
    const float* w = Wop + jj;
#pragma unroll 4
    for (int m = 0; m < H; m++) s += a[m] * w[m * H];
    g_WW[idx] = s;
}

__global__ void k_out0(const float* __restrict__ emb, float* __restrict__ out) {
    int idx = blockIdx.x * 256 + threadIdx.x;
    if (idx >= B * H) return;
    int b = idx / H, jj = idx - b * H;
    out[(size_t)b * T * H + jj] = emb[1 * H + jj];   // BOS = 1
}

// ------------------- persistent recurrence kernel (ONE launch, 32 steps) -------------------
// 148 blocks x 320 threads. Blocks 0..3 own 3 hh cols, 4..147 own 2. Weights [m][c][k]
// in smem once. Per step: whole h[t] staged into smem, pure LDS.128 dot with split
// accumulator chains, then a two-level flag barrier (no same-address atomics).
__global__ void __launch_bounds__(320, 1) k_steps(
        const float* __restrict__ Wi, const float* __restrict__ Wf,
        const float* __restrict__ Wo, const float* __restrict__ Wg,
        float* __restrict__ out) {
    extern __shared__ float smem[];
    float* xs = smem;                   // [b][300]  (pitch 300: conflict-free phases)
    float* sw = smem + 64 * 300;        // [m][c][300], 5*3*300
    float* ex = sw + 4500;              // gate exchange [gate][c*64+b]
    float* cs = ex + 768;               // cell state [c*64+b]

    int tid = threadIdx.x;
    int b = tid & 63, m = tid >> 6;          // m in [0,5)
    int bid = blockIdx.x;
    int nc  = (bid < 4) ? 3 : 2;
    int hh0 = (bid < 4) ? bid * 3 : 12 + (bid - 4) * 2;

    // ---- stage this block's weight slice into smem (once) ----
    for (int i = tid; i < 5 * 3 * 300; i += 320) {
        int k = i % 300, rc = i / 300;
        int mm = rc / 3, c = rc - mm * 3;
        if (c < nc) {
            float v;
            if (mm < 4) {
                const float* Wx = (mm == 0) ? Wi : (mm == 1) ? Wf : (mm == 2) ? Wo : Wg;
                v = Wx[(size_t)(300 + k) * H + hh0 + c];   // h rows of comb start at 300
            } else {
                v = g_WW[k * H + hh0 + c];
            }
            sw[i] = v;
        }
    }
    if (tid < nc * 64) {
        cs[tid] = g_cT[(hh0 + (tid >> 6)) * B + (tid & 63)];
    }
    __syncthreads();

    for (int t = 0; t < T; t++) {
        // ---- stage h[t] ([b][k] global, pitch 304) into xs ----
        const float4* hsrc = (const float4*)(g_hB + (size_t)t * 64 * HB_PITCH);
#pragma unroll
        for (int i = tid; i < 4800; i += 320) {
            int bb = i / 75, g = i - bb * 75;
            ((float4*)(xs + bb * 300))[g] = hsrc[bb * (HB_PITCH / 4) + g];
        }
        __syncthreads();

        bool gatew = (m < 4);
        bool act = gatew ? (t < 31) : (t > 0);
        float b0 = 0.f, b1 = 0.f, b2 = 0.f;
        if (act) {
            if (gatew) {
                int base = (t * 1200 + m * 300 + hh0) * B + b;
                b0 = g_baseT[base]; b1 = g_baseT[base + B];
                if (nc == 3) b2 = g_baseT[base + 2 * B];
            } else {
                int base = ((t - 1) * H + hh0) * B + b;
                b0 = g_pbT[base]; b1 = g_pbT[base + B];
                if (nc == 3) b2 = g_pbT[base + 2 * B];
            }
        }
        // split accumulator chains: xv.x lane -> *a, xv.y lane -> *b
        ull s0a = pk2(b0, 0.f), s0b = pk2(0.f, 0.f);
        ull s1a = pk2(b1, 0.f), s1b = pk2(0.f, 0.f);
        ull s2a = pk2(b2, 0.f), s2b = pk2(0.f, 0.f);
        if (act) {
            const ulonglong2* xp = (const ulonglong2*)(xs + b * 300);
            const ulonglong2* w0 = (const ulonglong2*)(sw + (m * 3 + 0) * 300);
            const ulonglong2* w1 = (const ulonglong2*)(sw + (m * 3 + 1) * 300);
            if (nc == 2) {
#pragma unroll 15
                for (int g = 0; g < 75; g++) {
                    ulonglong2 xv = xp[g];
                    ulonglong2 wa = w0[g];
                    fma2(s0a, xv.x, wa.x); fma2(s0b, xv.y, wa.y);
                    ulonglong2 wb = w1[g];
                    fma2(s1a, xv.x, wb.x); fma2(s1b, xv.y, wb.y);
                }
            } else {
                const ulonglong2* w2 = (const ulonglong2*)(sw + (m * 3 + 2) * 300);
#pragma unroll 15
                for (int g = 0; g < 75; g++) {
                    ulonglong2 xv = xp[g];
                    ulonglong2 wa = w0[g];
                    fma2(s0a, xv.x, wa.x); fma2(s0b, xv.y, wa.y);
                    ulonglong2 wb = w1[g];
                    fma2(s1a, xv.x, wb.x); fma2(s1b, xv.y, wb.y);
                    ulonglong2 wc = w2[g];
                    fma2(s2a, xv.x, wc.x); fma2(s2b, xv.y, wc.y);
                }
            }
        }
        float2 f0a = upk2(s0a), f0b = upk2(s0b);
        float2 f1a = upk2(s1a), f1b = upk2(s1b);
        float2 f2a = upk2(s2a), f2b = upk2(s2b);
        float r0 = (f0a.x + f0a.y) + (f0b.x + f0b.y);
        float r1 = (f1a.x + f1a.y) + (f1b.x + f1b.y);
        float r2 = (f2a.x + f2a.y) + (f2b.x + f2b.y);

        // ---- pred output (m==4) ----
        if (!gatew && t > 0) {
            size_t o = ((size_t)b * T + t) * H + hh0;
            out[o] = r0; out[o + 1] = r1;
            if (nc == 3) out[o + 2] = r2;
        }

        if (t < 31) {
            // ---- exchange gate pre-acts, pointwise LSTM update ----
            if (gatew) {
                ex[m * 192 + b]       = r0;
                ex[m * 192 + 64 + b]  = r1;
                if (nc == 3) ex[m * 192 + 128 + b] = r2;
            }
            __syncthreads();
            if (tid < nc * 64) {
                int c = tid >> 6, bb = tid & 63;
                float ai = ex[tid];
                float af = ex[192 + tid];
                float ao = ex[384 + tid];
                float ag = ex[576 + tid];
                float iv = 1.f / (1.f + expf(-ai));
                float fv = 1.f / (1.f + expf(-af));
                float ov = 1.f / (1.f + expf(-ao));
                float gv = tanhf(ag);
                float cn = fv * cs[tid] + iv * gv;
                cs[tid] = cn;
                g_hB[(size_t)(t + 1) * 64 * HB_PITCH + bb * HB_PITCH + hh0 + c] = ov * tanhf(cn);
            }
            // ---- two-level grid barrier (distinct-address flags + broadcast go) ----
            __threadfence();
            __syncthreads();
            unsigned tgt = (unsigned)(t + 1);
            if (bid == 0) {
                if (tid > 0 && tid < NBLK) {
                    while (g_arr[tid * 32] < tgt) { }
                }
                __syncthreads();
                if (tid == 0) { __threadfence(); g_go = tgt; }
            } else {
                if (tid == 0) {
                    g_arr[bid * 32] = tgt;
                    while (g_go < tgt) { }
                }
            }
            __syncthreads();
        }
    }
}

// ------------------- launch -------------------
extern "C" void kernel_launch(void* const* d_in, const int* in_sizes, int n_in,
                              void* d_out, int out_size) {
    const float* enc    = (const float*)d_in[0];
    const int*   caps   = (const int*)d_in[1];
    const float* emb    = (const float*)d_in[2];
    const float* Wh0    = (const float*)d_in[3];
    const float* bh0    = (const float*)d_in[4];
    const float* Wc0    = (const float*)d_in[5];
    const float* bc0    = (const float*)d_in[6];
    const float* We_enc = (const float*)d_in[7];
    // d_in[8] We_hid, d_in[9] be: unused — constant shifts inside softmax cancel.
    const float* Wi  = (const float*)d_in[10];
    const float* bi  = (const float*)d_in[11];
    const float* Wf  = (const float*)d_in[12];
    const float* bf  = (const float*)d_in[13];
    const float* Wo  = (const float*)d_in[14];
    const float* bo  = (const float*)d_in[15];
    const float* Wg  = (const float*)d_in[16];
    const float* bg  = (const float*)d_in[17];
    const float* Wcp = (const float*)d_in[18];
    const float* bcp = (const float*)d_in[19];
    const float* Whp = (const float*)d_in[20];
    const float* bhp = (const float*)d_in[21];
    const float* Wop = (const float*)d_in[22];
    const float* bop = (const float*)d_in[23];
    float* out = (float*)d_out;

    cudaFuncSetAttribute(k_steps, cudaFuncAttributeMaxDynamicSharedMemorySize, STEP_SMEM);

    k_eenc<<<1600, 128>>>(enc, We_enc);
    k_softmax<<<64, 128>>>();
    k_meanctx<<<256, 128>>>(enc);
    {
        dim3 gh(30, 8);
        k_h0c0p<<<gh, 320>>>(Wh0, Wc0);
    }
    k_h0red<<<150, 256>>>(bh0, bc0);
    {
        dim3 gc(75, 4);
        k_cwp<<<gc, 320>>>(Wi, Wf, Wo, Wg, Wcp);
    }
    k_cwred<<<375, 256>>>();
    {
        dim3 gb(60, 31);
        k_base<<<gb, 320>>>(caps, emb, Wi, Wf, Wo, Wg, bi, bf, bo, bg);
    }
    k_sb<<<(31 * H * B + 255) / 256, 256>>>(caps, emb, bcp, bhp);
    {
        dim3 gp(15, 31);
        k_pbase<<<gp, 320>>>(Wop, bop);
    }
    k_ww<<<(H * H + 255) / 256, 256>>>(Whp, Wop);
    k_out0<<<(B * H + 255) / 256, 256>>>(emb, out);

    k_steps<<<NBLK, 320, STEP_SMEM>>>(Wi, Wf, Wo, Wg, out);
}